// round 1
// baseline (speedup 1.0000x reference)
#include <cuda_runtime.h>

#define NP 76832          // 32 * 49 * 49 patches
#define HN 49
#define SLEN 104

// conv output scratch: (NP, 20*8*8) = (76832, 1280) floats
__device__ float g_h2[(size_t)NP * 1280];

// ---------------------------------------------------------------------------
// Kernel 1: per-patch conv1 (2->20, 3x3 SAME) + conv2 (20->20, 3x3 SAME), relu
// 4 patches per 256-thread block; one thread per output pixel.
// ---------------------------------------------------------------------------
__global__ __launch_bounds__(256) void conv_kernel(
    const float* __restrict__ images,
    const float* __restrict__ w1, const float* __restrict__ b1,
    const float* __restrict__ w2, const float* __restrict__ b2)
{
    __shared__ __align__(16) float s_in[4 * 2 * 100];    // padded 10x10 input
    __shared__ __align__(16) float s_h1[4 * 20 * 100];   // padded 10x10 conv1 out
    __shared__ __align__(16) float s_w1[20 * 2 * 12];    // taps padded 9->12
    __shared__ __align__(16) float s_w2[20 * 20 * 12];
    __shared__ float s_b1[20], s_b2[20];

    const int tid = threadIdx.x;

    // stage weights (taps padded to 12 floats for aligned float4 reads)
    for (int i = tid; i < 20 * 2 * 9; i += 256) {
        int oc = i / 18, r = i % 18, ic = r / 9, t = r % 9;
        s_w1[(oc * 2 + ic) * 12 + t] = w1[i];
    }
    for (int i = tid; i < 20 * 20 * 9; i += 256) {
        int oc = i / 180, r = i % 180, ic = r / 9, t = r % 9;
        s_w2[(oc * 20 + ic) * 12 + t] = w2[i];
    }
    if (tid < 20) { s_b1[tid] = b1[tid]; s_b2[tid] = b2[tid]; }

    // zero padded borders (interior gets overwritten)
    for (int i = tid; i < 4 * 2 * 100; i += 256) s_in[i] = 0.f;
    for (int i = tid; i < 4 * 20 * 100; i += 256) s_h1[i] = 0.f;
    __syncthreads();

    const int lp  = tid >> 6;         // local patch 0..3
    const int pix = tid & 63;
    const int y = pix >> 3, x = pix & 7;
    const int patch = blockIdx.x * 4 + lp;          // grid chosen so always < NP
    const int b  = patch / (HN * HN);
    const int t2 = patch % (HN * HN);
    const int i0 = (t2 / HN) * 2, j0 = (t2 % HN) * 2;

    // load patch input into padded smem tile
    #pragma unroll
    for (int c = 0; c < 2; c++) {
        s_in[(lp * 2 + c) * 100 + (y + 1) * 10 + (x + 1)] =
            images[((size_t)(b * 2 + c) * SLEN + (i0 + y)) * SLEN + (j0 + x)];
    }
    __syncthreads();

    // ---- conv1 ----
    {
        float v[2][9];
        #pragma unroll
        for (int c = 0; c < 2; c++)
            #pragma unroll
            for (int dy = 0; dy < 3; dy++)
                #pragma unroll
                for (int dx = 0; dx < 3; dx++)
                    v[c][dy * 3 + dx] = s_in[(lp * 2 + c) * 100 + (y + dy) * 10 + (x + dx)];
        #pragma unroll 5
        for (int oc = 0; oc < 20; oc++) {
            float acc = s_b1[oc];
            #pragma unroll
            for (int c = 0; c < 2; c++) {
                const float* w = &s_w1[(oc * 2 + c) * 12];
                float4 w0 = *(const float4*)(w);
                float4 w4 = *(const float4*)(w + 4);
                float  w8 = w[8];
                acc += v[c][0]*w0.x + v[c][1]*w0.y + v[c][2]*w0.z + v[c][3]*w0.w
                     + v[c][4]*w4.x + v[c][5]*w4.y + v[c][6]*w4.z + v[c][7]*w4.w
                     + v[c][8]*w8;
            }
            s_h1[(lp * 20 + oc) * 100 + (y + 1) * 10 + (x + 1)] = fmaxf(acc, 0.f);
        }
    }
    __syncthreads();

    // ---- conv2 ----
    {
        float acc[20];
        #pragma unroll
        for (int oc = 0; oc < 20; oc++) acc[oc] = s_b2[oc];
        for (int ic = 0; ic < 20; ic++) {
            float v[9];
            #pragma unroll
            for (int dy = 0; dy < 3; dy++)
                #pragma unroll
                for (int dx = 0; dx < 3; dx++)
                    v[dy * 3 + dx] = s_h1[(lp * 20 + ic) * 100 + (y + dy) * 10 + (x + dx)];
            #pragma unroll
            for (int oc = 0; oc < 20; oc++) {
                const float* w = &s_w2[(oc * 20 + ic) * 12];
                float4 w0 = *(const float4*)(w);
                float4 w4 = *(const float4*)(w + 4);
                float  w8 = w[8];
                acc[oc] += v[0]*w0.x + v[1]*w0.y + v[2]*w0.z + v[3]*w0.w
                         + v[4]*w4.x + v[5]*w4.y + v[6]*w4.z + v[7]*w4.w
                         + v[8]*w8;
            }
        }
        float* dst = &g_h2[(size_t)patch * 1280 + pix];
        #pragma unroll 5
        for (int oc = 0; oc < 20; oc++)
            dst[oc * 64] = fmaxf(acc[oc], 0.f);
    }
}

// ---------------------------------------------------------------------------
// Kernel 2: fused MLP fc1(1280->256)+relu, fc2, fc3, fcf(256->27)
// 64 rows per 256-thread block; 4x16 register tile per thread (64 acc).
// ---------------------------------------------------------------------------
__global__ __launch_bounds__(256, 1) void mlp_kernel(
    const float* __restrict__ fc1_w, const float* __restrict__ fc1_b,
    const float* __restrict__ fc2_w, const float* __restrict__ fc2_b,
    const float* __restrict__ fc3_w, const float* __restrict__ fc3_b,
    const float* __restrict__ fcf_w, const float* __restrict__ fcf_b,
    float* __restrict__ out)
{
    extern __shared__ __align__(16) float sm[];
    float* sA   = sm;                    // 16 x 64            (1024)
    float* sW   = sm + 1024;             // up to 27*257=6939  (pad to 6944)
    float* act1 = sm + 1024 + 6944;      // 64 x 260           (16640)
    float* act2 = act1 + 16640;          // 64 x 260           (16640)
    // total 41248 floats = 164992 bytes

    const int tid = threadIdx.x;
    const int tx = tid & 15, ty = tid >> 4;
    const int r0 = blockIdx.x * 64;

    float acc[4][16];

    // ================= fc1: K = 1280 =================
    #pragma unroll
    for (int u = 0; u < 4; u++)
        #pragma unroll
        for (int j = 0; j < 16; j++) acc[u][j] = 0.f;

    const int arow = tid >> 2, aquad = tid & 3;
    const bool avalid = (r0 + arow) < NP;
    const size_t agbase = (size_t)(r0 + arow) * 1280 + aquad * 4;

    for (int k0 = 0; k0 < 1280; k0 += 16) {
        float4 av = make_float4(0.f, 0.f, 0.f, 0.f);
        if (avalid) av = *(const float4*)&g_h2[agbase + k0];
        sA[(aquad * 4 + 0) * 64 + arow] = av.x;
        sA[(aquad * 4 + 1) * 64 + arow] = av.y;
        sA[(aquad * 4 + 2) * 64 + arow] = av.z;
        sA[(aquad * 4 + 3) * 64 + arow] = av.w;
        {
            const float* wp = &fc1_w[(size_t)tid * 1280 + k0];
            float4 q0 = *(const float4*)(wp);
            float4 q1 = *(const float4*)(wp + 4);
            float4 q2 = *(const float4*)(wp + 8);
            float4 q3 = *(const float4*)(wp + 12);
            sW[ 0*256+tid]=q0.x; sW[ 1*256+tid]=q0.y; sW[ 2*256+tid]=q0.z; sW[ 3*256+tid]=q0.w;
            sW[ 4*256+tid]=q1.x; sW[ 5*256+tid]=q1.y; sW[ 6*256+tid]=q1.z; sW[ 7*256+tid]=q1.w;
            sW[ 8*256+tid]=q2.x; sW[ 9*256+tid]=q2.y; sW[10*256+tid]=q2.z; sW[11*256+tid]=q2.w;
            sW[12*256+tid]=q3.x; sW[13*256+tid]=q3.y; sW[14*256+tid]=q3.z; sW[15*256+tid]=q3.w;
        }
        __syncthreads();
        #pragma unroll
        for (int kk = 0; kk < 16; kk++) {
            float a0 = sA[kk * 64 + ty * 4 + 0];
            float a1 = sA[kk * 64 + ty * 4 + 1];
            float a2 = sA[kk * 64 + ty * 4 + 2];
            float a3 = sA[kk * 64 + ty * 4 + 3];
            #pragma unroll
            for (int j = 0; j < 16; j++) {
                float bv = sW[kk * 256 + tx + 16 * j];
                acc[0][j] += a0 * bv;
                acc[1][j] += a1 * bv;
                acc[2][j] += a2 * bv;
                acc[3][j] += a3 * bv;
            }
        }
        __syncthreads();
    }
    {
        float bb[16];
        #pragma unroll
        for (int j = 0; j < 16; j++) bb[j] = fc1_b[tx + 16 * j];
        #pragma unroll
        for (int u = 0; u < 4; u++)
            #pragma unroll
            for (int j = 0; j < 16; j++)
                act1[(ty * 4 + u) * 260 + tx + 16 * j] = fmaxf(acc[u][j] + bb[j], 0.f);
    }

    // ================= fc2: K = 256 (act1 -> act2) =================
    #pragma unroll
    for (int u = 0; u < 4; u++)
        #pragma unroll
        for (int j = 0; j < 16; j++) acc[u][j] = 0.f;
    for (int k0 = 0; k0 < 256; k0 += 16) {
        const float* wp = &fc2_w[(size_t)tid * 256 + k0];
        float4 q0 = *(const float4*)(wp);
        float4 q1 = *(const float4*)(wp + 4);
        float4 q2 = *(const float4*)(wp + 8);
        float4 q3 = *(const float4*)(wp + 12);
        sW[ 0*256+tid]=q0.x; sW[ 1*256+tid]=q0.y; sW[ 2*256+tid]=q0.z; sW[ 3*256+tid]=q0.w;
        sW[ 4*256+tid]=q1.x; sW[ 5*256+tid]=q1.y; sW[ 6*256+tid]=q1.z; sW[ 7*256+tid]=q1.w;
        sW[ 8*256+tid]=q2.x; sW[ 9*256+tid]=q2.y; sW[10*256+tid]=q2.z; sW[11*256+tid]=q2.w;
        sW[12*256+tid]=q3.x; sW[13*256+tid]=q3.y; sW[14*256+tid]=q3.z; sW[15*256+tid]=q3.w;
        __syncthreads();
        #pragma unroll
        for (int kk = 0; kk < 16; kk++) {
            float a0 = act1[(ty * 4 + 0) * 260 + k0 + kk];
            float a1 = act1[(ty * 4 + 1) * 260 + k0 + kk];
            float a2 = act1[(ty * 4 + 2) * 260 + k0 + kk];
            float a3 = act1[(ty * 4 + 3) * 260 + k0 + kk];
            #pragma unroll
            for (int j = 0; j < 16; j++) {
                float bv = sW[kk * 256 + tx + 16 * j];
                acc[0][j] += a0 * bv;
                acc[1][j] += a1 * bv;
                acc[2][j] += a2 * bv;
                acc[3][j] += a3 * bv;
            }
        }
        __syncthreads();
    }
    {
        float bb[16];
        #pragma unroll
        for (int j = 0; j < 16; j++) bb[j] = fc2_b[tx + 16 * j];
        #pragma unroll
        for (int u = 0; u < 4; u++)
            #pragma unroll
            for (int j = 0; j < 16; j++)
                act2[(ty * 4 + u) * 260 + tx + 16 * j] = fmaxf(acc[u][j] + bb[j], 0.f);
    }

    // ================= fc3: K = 256 (act2 -> act1) =================
    #pragma unroll
    for (int u = 0; u < 4; u++)
        #pragma unroll
        for (int j = 0; j < 16; j++) acc[u][j] = 0.f;
    for (int k0 = 0; k0 < 256; k0 += 16) {
        const float* wp = &fc3_w[(size_t)tid * 256 + k0];
        float4 q0 = *(const float4*)(wp);
        float4 q1 = *(const float4*)(wp + 4);
        float4 q2 = *(const float4*)(wp + 8);
        float4 q3 = *(const float4*)(wp + 12);
        sW[ 0*256+tid]=q0.x; sW[ 1*256+tid]=q0.y; sW[ 2*256+tid]=q0.z; sW[ 3*256+tid]=q0.w;
        sW[ 4*256+tid]=q1.x; sW[ 5*256+tid]=q1.y; sW[ 6*256+tid]=q1.z; sW[ 7*256+tid]=q1.w;
        sW[ 8*256+tid]=q2.x; sW[ 9*256+tid]=q2.y; sW[10*256+tid]=q2.z; sW[11*256+tid]=q2.w;
        sW[12*256+tid]=q3.x; sW[13*256+tid]=q3.y; sW[14*256+tid]=q3.z; sW[15*256+tid]=q3.w;
        __syncthreads();
        #pragma unroll
        for (int kk = 0; kk < 16; kk++) {
            float a0 = act2[(ty * 4 + 0) * 260 + k0 + kk];
            float a1 = act2[(ty * 4 + 1) * 260 + k0 + kk];
            float a2 = act2[(ty * 4 + 2) * 260 + k0 + kk];
            float a3 = act2[(ty * 4 + 3) * 260 + k0 + kk];
            #pragma unroll
            for (int j = 0; j < 16; j++) {
                float bv = sW[kk * 256 + tx + 16 * j];
                acc[0][j] += a0 * bv;
                acc[1][j] += a1 * bv;
                acc[2][j] += a2 * bv;
                acc[3][j] += a3 * bv;
            }
        }
        __syncthreads();
    }
    {
        float bb[16];
        #pragma unroll
        for (int j = 0; j < 16; j++) bb[j] = fc3_b[tx + 16 * j];
        #pragma unroll
        for (int u = 0; u < 4; u++)
            #pragma unroll
            for (int j = 0; j < 16; j++)
                act1[(ty * 4 + u) * 260 + tx + 16 * j] = fmaxf(acc[u][j] + bb[j], 0.f);
    }

    // ================= fcf: 256 -> 27 =================
    // stage fcf_w into sW with row stride 257 (conflict-free for o-varying lanes)
    for (int i = tid; i < 27 * 256; i += 256) {
        int o = i >> 8, k = i & 255;
        sW[o * 257 + k] = fcf_w[i];
    }
    __syncthreads();

    for (int idx = tid; idx < 64 * 27; idx += 256) {
        int m = idx / 27;
        int o = idx - m * 27;
        if (r0 + m < NP) {
            float s = fcf_b[o];
            const float* ar = &act1[m * 260];
            const float* wr = &sW[o * 257];
            #pragma unroll 4
            for (int k = 0; k < 256; k += 4) {
                float4 a4 = *(const float4*)(ar + k);
                s += a4.x * wr[k + 0];
                s += a4.y * wr[k + 1];
                s += a4.z * wr[k + 2];
                s += a4.w * wr[k + 3];
            }
            out[(size_t)(r0 + m) * 27 + o] = s;
        }
    }
}

// ---------------------------------------------------------------------------
extern "C" void kernel_launch(void* const* d_in, const int* in_sizes, int n_in,
                              void* d_out, int out_size)
{
    const float* images  = (const float*)d_in[0];
    const float* conv1_w = (const float*)d_in[1];
    const float* conv1_b = (const float*)d_in[2];
    const float* conv2_w = (const float*)d_in[3];
    const float* conv2_b = (const float*)d_in[4];
    const float* fc1_w   = (const float*)d_in[5];
    const float* fc1_b   = (const float*)d_in[6];
    const float* fc2_w   = (const float*)d_in[7];
    const float* fc2_b   = (const float*)d_in[8];
    const float* fc3_w   = (const float*)d_in[9];
    const float* fc3_b   = (const float*)d_in[10];
    const float* fcf_w   = (const float*)d_in[11];
    const float* fcf_b   = (const float*)d_in[12];
    float* out = (float*)d_out;

    // conv: 76832 patches, 4 per block
    conv_kernel<<<NP / 4, 256>>>(images, conv1_w, conv1_b, conv2_w, conv2_b);

    // mlp: 64 rows per block
    const size_t smem2 = 41248 * sizeof(float);  // 164992 B
    cudaFuncSetAttribute(mlp_kernel, cudaFuncAttributeMaxDynamicSharedMemorySize,
                         (int)smem2);
    mlp_kernel<<<(NP + 63) / 64, 256, smem2>>>(
        fc1_w, fc1_b, fc2_w, fc2_b, fc3_w, fc3_b, fcf_w, fcf_b, out);
}

// round 3
// speedup vs baseline: 2.1479x; 2.1479x over previous
#include <cuda_runtime.h>
#include <cstdint>

#define NP 76832          // 32 * 49 * 49 patches
#define HN 49
#define SLEN 104
#define MROWS_PAD 76928   // 601 * 128

// conv output scratch (zero-initialized device global; pad rows stay zero)
__device__ float g_h2[(size_t)MROWS_PAD * 1280];

__device__ __forceinline__ float to_tf32(float x) {
    float r; asm("cvt.rna.tf32.f32 %0, %1;" : "=f"(r) : "f"(x)); return r;
}
__device__ __forceinline__ void mma_tf32(float* c, uint32_t a0, uint32_t a1,
                                         uint32_t a2, uint32_t a3,
                                         uint32_t b0, uint32_t b1) {
    asm volatile(
        "mma.sync.aligned.m16n8k8.row.col.f32.tf32.tf32.f32 "
        "{%0,%1,%2,%3}, {%4,%5,%6,%7}, {%8,%9}, {%0,%1,%2,%3};"
        : "+f"(c[0]), "+f"(c[1]), "+f"(c[2]), "+f"(c[3])
        : "r"(a0), "r"(a1), "r"(a2), "r"(a3), "r"(b0), "r"(b1));
}
#define F2U(x) __float_as_uint(x)

// ---------------------------------------------------------------------------
// Kernel 1 (unchanged): per-patch conv1 + conv2, relu
// ---------------------------------------------------------------------------
__global__ __launch_bounds__(256) void conv_kernel(
    const float* __restrict__ images,
    const float* __restrict__ w1, const float* __restrict__ b1,
    const float* __restrict__ w2, const float* __restrict__ b2)
{
    __shared__ __align__(16) float s_in[4 * 2 * 100];
    __shared__ __align__(16) float s_h1[4 * 20 * 100];
    __shared__ __align__(16) float s_w1[20 * 2 * 12];
    __shared__ __align__(16) float s_w2[20 * 20 * 12];
    __shared__ float s_b1[20], s_b2[20];

    const int tid = threadIdx.x;

    for (int i = tid; i < 20 * 2 * 9; i += 256) {
        int oc = i / 18, r = i % 18, ic = r / 9, t = r % 9;
        s_w1[(oc * 2 + ic) * 12 + t] = w1[i];
    }
    for (int i = tid; i < 20 * 20 * 9; i += 256) {
        int oc = i / 180, r = i % 180, ic = r / 9, t = r % 9;
        s_w2[(oc * 20 + ic) * 12 + t] = w2[i];
    }
    if (tid < 20) { s_b1[tid] = b1[tid]; s_b2[tid] = b2[tid]; }

    for (int i = tid; i < 4 * 2 * 100; i += 256) s_in[i] = 0.f;
    for (int i = tid; i < 4 * 20 * 100; i += 256) s_h1[i] = 0.f;
    __syncthreads();

    const int lp  = tid >> 6;
    const int pix = tid & 63;
    const int y = pix >> 3, x = pix & 7;
    const int patch = blockIdx.x * 4 + lp;
    const int b  = patch / (HN * HN);
    const int t2 = patch % (HN * HN);
    const int i0 = (t2 / HN) * 2, j0 = (t2 % HN) * 2;

    #pragma unroll
    for (int c = 0; c < 2; c++) {
        s_in[(lp * 2 + c) * 100 + (y + 1) * 10 + (x + 1)] =
            images[((size_t)(b * 2 + c) * SLEN + (i0 + y)) * SLEN + (j0 + x)];
    }
    __syncthreads();

    {
        float v[2][9];
        #pragma unroll
        for (int c = 0; c < 2; c++)
            #pragma unroll
            for (int dy = 0; dy < 3; dy++)
                #pragma unroll
                for (int dx = 0; dx < 3; dx++)
                    v[c][dy * 3 + dx] = s_in[(lp * 2 + c) * 100 + (y + dy) * 10 + (x + dx)];
        #pragma unroll 5
        for (int oc = 0; oc < 20; oc++) {
            float acc = s_b1[oc];
            #pragma unroll
            for (int c = 0; c < 2; c++) {
                const float* w = &s_w1[(oc * 2 + c) * 12];
                float4 w0 = *(const float4*)(w);
                float4 w4 = *(const float4*)(w + 4);
                float  w8 = w[8];
                acc += v[c][0]*w0.x + v[c][1]*w0.y + v[c][2]*w0.z + v[c][3]*w0.w
                     + v[c][4]*w4.x + v[c][5]*w4.y + v[c][6]*w4.z + v[c][7]*w4.w
                     + v[c][8]*w8;
            }
            s_h1[(lp * 20 + oc) * 100 + (y + 1) * 10 + (x + 1)] = fmaxf(acc, 0.f);
        }
    }
    __syncthreads();

    {
        float acc[20];
        #pragma unroll
        for (int oc = 0; oc < 20; oc++) acc[oc] = s_b2[oc];
        for (int ic = 0; ic < 20; ic++) {
            float v[9];
            #pragma unroll
            for (int dy = 0; dy < 3; dy++)
                #pragma unroll
                for (int dx = 0; dx < 3; dx++)
                    v[dy * 3 + dx] = s_h1[(lp * 20 + ic) * 100 + (y + dy) * 10 + (x + dx)];
            #pragma unroll
            for (int oc = 0; oc < 20; oc++) {
                const float* w = &s_w2[(oc * 20 + ic) * 12];
                float4 w0 = *(const float4*)(w);
                float4 w4 = *(const float4*)(w + 4);
                float  w8 = w[8];
                acc[oc] += v[0]*w0.x + v[1]*w0.y + v[2]*w0.z + v[3]*w0.w
                         + v[4]*w4.x + v[5]*w4.y + v[6]*w4.z + v[7]*w4.w
                         + v[8]*w8;
            }
        }
        float* dst = &g_h2[(size_t)patch * 1280 + pix];
        #pragma unroll 5
        for (int oc = 0; oc < 20; oc++)
            dst[oc * 64] = fmaxf(acc[oc], 0.f);
    }
}

// ---------------------------------------------------------------------------
// Kernel 2: fused MLP on mma.sync tf32.
// 512 threads = 16 warps (4x4). CTA tile M=128, N=256. Warp tile 32x64.
// K chunks of 32, register-staged prefetch. Activations resident in smem.
// ---------------------------------------------------------------------------
#define LDACT 260
#define LDB   36
// smem float offsets
#define SACT 0                       // 128*260 = 33280
#define SB   33280                   // 256*36  = 9216
#define SAF  (33280 + 9216)          // 128*36  = 4608
#define SMEM_FLOATS (33280 + 9216 + 4608)

__global__ __launch_bounds__(512, 1) void mlp_mma_kernel(
    const float* __restrict__ fc1_w, const float* __restrict__ fc1_b,
    const float* __restrict__ fc2_w, const float* __restrict__ fc2_b,
    const float* __restrict__ fc3_w, const float* __restrict__ fc3_b,
    const float* __restrict__ fcf_w, const float* __restrict__ fcf_b,
    float* __restrict__ out)
{
    extern __shared__ __align__(16) float sm[];
    float* sAct = sm + SACT;
    float* sB   = sm + SB;
    float* sA   = sm + SAF;

    const int tid  = threadIdx.x;
    const int lane = tid & 31;
    const int wid  = tid >> 5;
    const int wm   = wid >> 2;        // 0..3  (M)
    const int wn   = wid & 3;         // 0..3  (N)
    const int g    = lane >> 2;       // 0..7
    const int tig  = lane & 3;        // 0..3
    const int m0   = blockIdx.x * 128;

    const int sr = tid >> 3, sf = tid & 7;   // staging coords (r = quad row, f)

    float acc[2][8][4];
    float4 bst[4];
    float4 ast[2];

    // =============== fc1: K=1280, A streamed from g_h2 ===============
    {
        const int NC = 40;
        #pragma unroll
        for (int mt = 0; mt < 2; mt++)
            #pragma unroll
            for (int nt = 0; nt < 8; nt++)
                #pragma unroll
                for (int q = 0; q < 4; q++) acc[mt][nt][q] = 0.f;

        // prefetch chunk 0
        #pragma unroll
        for (int p = 0; p < 4; p++)
            bst[p] = *(const float4*)&fc1_w[(size_t)(sr + p * 64) * 1280 + sf * 4];
        #pragma unroll
        for (int p = 0; p < 2; p++)
            ast[p] = *(const float4*)&g_h2[(size_t)(m0 + sr + p * 64) * 1280 + sf * 4];

        for (int c = 0; c < NC; c++) {
            __syncthreads();
            #pragma unroll
            for (int p = 0; p < 4; p++) {
                float4 v = bst[p];
                v.x = to_tf32(v.x); v.y = to_tf32(v.y);
                v.z = to_tf32(v.z); v.w = to_tf32(v.w);
                *(float4*)&sB[(sr + p * 64) * LDB + sf * 4] = v;
            }
            #pragma unroll
            for (int p = 0; p < 2; p++) {
                float4 v = ast[p];
                v.x = to_tf32(v.x); v.y = to_tf32(v.y);
                v.z = to_tf32(v.z); v.w = to_tf32(v.w);
                *(float4*)&sA[(sr + p * 64) * LDB + sf * 4] = v;
            }
            __syncthreads();
            if (c + 1 < NC) {
                const int k0 = (c + 1) * 32;
                #pragma unroll
                for (int p = 0; p < 4; p++)
                    bst[p] = *(const float4*)&fc1_w[(size_t)(sr + p * 64) * 1280 + k0 + sf * 4];
                #pragma unroll
                for (int p = 0; p < 2; p++)
                    ast[p] = *(const float4*)&g_h2[(size_t)(m0 + sr + p * 64) * 1280 + k0 + sf * 4];
            }
            #pragma unroll
            for (int k8 = 0; k8 < 4; k8++) {
                const int kk = k8 * 8;
                uint32_t a[2][4];
                #pragma unroll
                for (int mt = 0; mt < 2; mt++) {
                    const int r = (wm * 32 + mt * 16 + g) * LDB + kk + tig;
                    a[mt][0] = F2U(sA[r]);
                    a[mt][1] = F2U(sA[r + 8 * LDB]);
                    a[mt][2] = F2U(sA[r + 4]);
                    a[mt][3] = F2U(sA[r + 8 * LDB + 4]);
                }
                #pragma unroll
                for (int nt = 0; nt < 8; nt++) {
                    const int nb = (wn * 64 + nt * 8 + g) * LDB + kk + tig;
                    uint32_t b0 = F2U(sB[nb]);
                    uint32_t b1 = F2U(sB[nb + 4]);
                    mma_tf32(acc[0][nt], a[0][0], a[0][1], a[0][2], a[0][3], b0, b1);
                    mma_tf32(acc[1][nt], a[1][0], a[1][1], a[1][2], a[1][3], b0, b1);
                }
            }
        }
        __syncthreads();
        // epilogue -> sAct
        #pragma unroll
        for (int mt = 0; mt < 2; mt++)
            #pragma unroll
            for (int nt = 0; nt < 8; nt++) {
                const int row = wm * 32 + mt * 16 + g;
                const int col = wn * 64 + nt * 8 + tig * 2;
                const float bv0 = fc1_b[col], bv1 = fc1_b[col + 1];
                sAct[row * LDACT + col]           = to_tf32(fmaxf(acc[mt][nt][0] + bv0, 0.f));
                sAct[row * LDACT + col + 1]       = to_tf32(fmaxf(acc[mt][nt][1] + bv1, 0.f));
                sAct[(row + 8) * LDACT + col]     = to_tf32(fmaxf(acc[mt][nt][2] + bv0, 0.f));
                sAct[(row + 8) * LDACT + col + 1] = to_tf32(fmaxf(acc[mt][nt][3] + bv1, 0.f));
            }
        __syncthreads();
    }

    // =============== fc2 & fc3: K=256, A resident in sAct ===============
    for (int layer = 0; layer < 2; layer++) {
        const float* wg = layer ? fc3_w : fc2_w;
        const float* bg = layer ? fc3_b : fc2_b;
        const int NC = 8;
        #pragma unroll
        for (int mt = 0; mt < 2; mt++)
            #pragma unroll
            for (int nt = 0; nt < 8; nt++)
                #pragma unroll
                for (int q = 0; q < 4; q++) acc[mt][nt][q] = 0.f;

        #pragma unroll
        for (int p = 0; p < 4; p++)
            bst[p] = *(const float4*)&wg[(size_t)(sr + p * 64) * 256 + sf * 4];

        for (int c = 0; c < NC; c++) {
            __syncthreads();
            #pragma unroll
            for (int p = 0; p < 4; p++) {
                float4 v = bst[p];
                v.x = to_tf32(v.x); v.y = to_tf32(v.y);
                v.z = to_tf32(v.z); v.w = to_tf32(v.w);
                *(float4*)&sB[(sr + p * 64) * LDB + sf * 4] = v;
            }
            __syncthreads();
            if (c + 1 < NC) {
                const int k0 = (c + 1) * 32;
                #pragma unroll
                for (int p = 0; p < 4; p++)
                    bst[p] = *(const float4*)&wg[(size_t)(sr + p * 64) * 256 + k0 + sf * 4];
            }
            const int cb = c * 32;
            #pragma unroll
            for (int k8 = 0; k8 < 4; k8++) {
                const int kk = cb + k8 * 8;
                uint32_t a[2][4];
                #pragma unroll
                for (int mt = 0; mt < 2; mt++) {
                    const int r = (wm * 32 + mt * 16 + g) * LDACT + kk + tig;
                    a[mt][0] = F2U(sAct[r]);
                    a[mt][1] = F2U(sAct[r + 8 * LDACT]);
                    a[mt][2] = F2U(sAct[r + 4]);
                    a[mt][3] = F2U(sAct[r + 8 * LDACT + 4]);
                }
                #pragma unroll
                for (int nt = 0; nt < 8; nt++) {
                    const int nb = (wn * 64 + nt * 8 + g) * LDB + (k8 * 8) + tig;
                    uint32_t b0 = F2U(sB[nb]);
                    uint32_t b1 = F2U(sB[nb + 4]);
                    mma_tf32(acc[0][nt], a[0][0], a[0][1], a[0][2], a[0][3], b0, b1);
                    mma_tf32(acc[1][nt], a[1][0], a[1][1], a[1][2], a[1][3], b0, b1);
                }
            }
        }
        __syncthreads();
        #pragma unroll
        for (int mt = 0; mt < 2; mt++)
            #pragma unroll
            for (int nt = 0; nt < 8; nt++) {
                const int row = wm * 32 + mt * 16 + g;
                const int col = wn * 64 + nt * 8 + tig * 2;
                const float bv0 = bg[col], bv1 = bg[col + 1];
                sAct[row * LDACT + col]           = to_tf32(fmaxf(acc[mt][nt][0] + bv0, 0.f));
                sAct[row * LDACT + col + 1]       = to_tf32(fmaxf(acc[mt][nt][1] + bv1, 0.f));
                sAct[(row + 8) * LDACT + col]     = to_tf32(fmaxf(acc[mt][nt][2] + bv0, 0.f));
                sAct[(row + 8) * LDACT + col + 1] = to_tf32(fmaxf(acc[mt][nt][3] + bv1, 0.f));
            }
        __syncthreads();
    }

    // =============== fcf: K=256, N=27 (pad 32), warp n-tile = 8 ===============
    {
        #pragma unroll
        for (int mt = 0; mt < 2; mt++)
            #pragma unroll
            for (int q = 0; q < 4; q++) acc[mt][0][q] = 0.f;

        // stage all of fcf_w once: rows 0..31 (zero >=27), K=256 -> sB as [32][260]
        // reuse sB+sA region? sB has 9216 floats; need 32*260=8320 -> fits in sB.
        for (int i = tid; i < 32 * 64; i += 512) {
            int r = i >> 6, f = i & 63;            // f: 4-float group
            float4 v = make_float4(0.f, 0.f, 0.f, 0.f);
            if (r < 27) v = *(const float4*)&fcf_w[(size_t)r * 256 + f * 4];
            v.x = to_tf32(v.x); v.y = to_tf32(v.y);
            v.z = to_tf32(v.z); v.w = to_tf32(v.w);
            *(float4*)&sB[r * LDACT + f * 4] = v;
        }
        __syncthreads();

        #pragma unroll 4
        for (int k8 = 0; k8 < 32; k8++) {
            const int kk = k8 * 8;
            uint32_t a[2][4];
            #pragma unroll
            for (int mt = 0; mt < 2; mt++) {
                const int r = (wm * 32 + mt * 16 + g) * LDACT + kk + tig;
                a[mt][0] = F2U(sAct[r]);
                a[mt][1] = F2U(sAct[r + 8 * LDACT]);
                a[mt][2] = F2U(sAct[r + 4]);
                a[mt][3] = F2U(sAct[r + 8 * LDACT + 4]);
            }
            const int nb = (wn * 8 + g) * LDACT + kk + tig;
            uint32_t b0 = F2U(sB[nb]);
            uint32_t b1 = F2U(sB[nb + 4]);
            mma_tf32(acc[0][0], a[0][0], a[0][1], a[0][2], a[0][3], b0, b1);
            mma_tf32(acc[1][0], a[1][0], a[1][1], a[1][2], a[1][3], b0, b1);
        }

        // write out: D[128, 27]
        #pragma unroll
        for (int mt = 0; mt < 2; mt++) {
            const int row = m0 + wm * 32 + mt * 16 + g;
            const int col = wn * 8 + tig * 2;
            #pragma unroll
            for (int h = 0; h < 2; h++) {          // h: +8 row offset via regs 2,3
                const int rr = row + h * 8;
                if (rr < NP) {
                    if (col < 27)
                        out[(size_t)rr * 27 + col] = acc[mt][0][h * 2 + 0] + fcf_b[col];
                    if (col + 1 < 27)
                        out[(size_t)rr * 27 + col + 1] = acc[mt][0][h * 2 + 1] + fcf_b[col + 1];
                }
            }
        }
    }
}

// ---------------------------------------------------------------------------
extern "C" void kernel_launch(void* const* d_in, const int* in_sizes, int n_in,
                              void* d_out, int out_size)
{
    const float* images  = (const float*)d_in[0];
    const float* conv1_w = (const float*)d_in[1];
    const float* conv1_b = (const float*)d_in[2];
    const float* conv2_w = (const float*)d_in[3];
    const float* conv2_b = (const float*)d_in[4];
    const float* fc1_w   = (const float*)d_in[5];
    const float* fc1_b   = (const float*)d_in[6];
    const float* fc2_w   = (const float*)d_in[7];
    const float* fc2_b   = (const float*)d_in[8];
    const float* fc3_w   = (const float*)d_in[9];
    const float* fc3_b   = (const float*)d_in[10];
    const float* fcf_w   = (const float*)d_in[11];
    const float* fcf_b   = (const float*)d_in[12];
    float* out = (float*)d_out;

    conv_kernel<<<NP / 4, 256>>>(images, conv1_w, conv1_b, conv2_w, conv2_b);

    const size_t smem2 = SMEM_FLOATS * sizeof(float);   // 188,416 B
    cudaFuncSetAttribute(mlp_mma_kernel,
                         cudaFuncAttributeMaxDynamicSharedMemorySize, (int)smem2);
    mlp_mma_kernel<<<MROWS_PAD / 128, 512, smem2>>>(
        fc1_w, fc1_b, fc2_w, fc2_b, fc3_w, fc3_b, fcf_w, fcf_b, out);
}

// round 6
// speedup vs baseline: 3.4722x; 1.6166x over previous
#include <cuda_runtime.h>
#include <cstdint>

#define NP 76832          // 32 * 49 * 49 patches
#define HN 49
#define SLEN 104
#define MROWS_PAD 76928   // 601 * 128

// conv output scratch (zero-initialized device global; pad rows stay zero)
__device__ float g_h2[(size_t)MROWS_PAD * 1280];

__device__ __forceinline__ float to_tf32(float x) {
    float r; asm("cvt.rna.tf32.f32 %0, %1;" : "=f"(r) : "f"(x)); return r;
}
__device__ __forceinline__ void mma_tf32(float* c, uint32_t a0, uint32_t a1,
                                         uint32_t a2, uint32_t a3,
                                         uint32_t b0, uint32_t b1) {
    asm volatile(
        "mma.sync.aligned.m16n8k8.row.col.f32.tf32.tf32.f32 "
        "{%0,%1,%2,%3}, {%4,%5,%6,%7}, {%8,%9}, {%0,%1,%2,%3};"
        : "+f"(c[0]), "+f"(c[1]), "+f"(c[2]), "+f"(c[3])
        : "r"(a0), "r"(a1), "r"(a2), "r"(a3), "r"(b0), "r"(b1));
}
#define F2U(x) __float_as_uint(x)

// ===========================================================================
// Kernel 1: conv1 (FFMA) + conv2 (mma.sync tf32 tap-wise implicit GEMM)
// 8 patches / CTA, 512 threads = 16 warps. M=512 pixels, N=24(20), K=24(20)/tap
// ===========================================================================
// smem float offsets
#define C_SH1  0                 // 8 patches x 24 ic x 104 (padded 10x10) = 19968
#define C_SW2  19968             // 9 taps x 24 oc x 25 = 5400
#define C_SIN  25368             // 8 x 2 x 100 = 1600
#define C_SW1  26968             // 480
#define C_SB1  27448             // 20
#define C_SB2  27468             // 24
#define C_SMEM_FLOATS 27492      // 109,968 bytes

__global__ __launch_bounds__(512, 1) void conv_mma_kernel(
    const float* __restrict__ images,
    const float* __restrict__ w1, const float* __restrict__ b1,
    const float* __restrict__ w2, const float* __restrict__ b2)
{
    extern __shared__ __align__(16) float sm[];
    float* sH1 = sm + C_SH1;
    float* sW2 = sm + C_SW2;
    float* sIn = sm + C_SIN;
    float* sW1 = sm + C_SW1;
    float* sB1 = sm + C_SB1;
    float* sB2 = sm + C_SB2;

    const int tid = threadIdx.x;

    // ---- zero-fill padded regions ----
    for (int i = tid; i < 19968; i += 512) sH1[i] = 0.f;
    for (int i = tid; i < 5400;  i += 512) sW2[i] = 0.f;
    for (int i = tid; i < 1600;  i += 512) sIn[i] = 0.f;

    // ---- stage weights ----
    for (int i = tid; i < 20 * 2 * 9; i += 512) {
        int oc = i / 18, r = i % 18, ic = r / 9, t = r % 9;
        sW1[(oc * 2 + ic) * 12 + t] = w1[i];
    }
    if (tid < 20) sB1[tid] = b1[tid];
    if (tid < 24) sB2[tid] = (tid < 20) ? b2[tid] : 0.f;
    __syncthreads();   // zero-fill of sW2 must complete before scatter

    // w2 (OIHW) -> sW2[tap][oc][25] (rna tf32)
    for (int i = tid; i < 20 * 180; i += 512) {
        int oc = i / 180, r = i % 180, ic = r / 9, tap = r % 9;
        sW2[tap * 600 + oc * 25 + ic] = to_tf32(w2[i]);
    }

    // ---- load input patches ----
    const int lp  = tid >> 6;           // 0..7
    const int pix = tid & 63;
    const int y = pix >> 3, x = pix & 7;
    const int patch = blockIdx.x * 8 + lp;
    const int b  = patch / (HN * HN);
    const int t2 = patch % (HN * HN);
    const int i0 = (t2 / HN) * 2, j0 = (t2 % HN) * 2;

    #pragma unroll
    for (int c = 0; c < 2; c++) {
        sIn[(lp * 2 + c) * 100 + (y + 1) * 10 + (x + 1)] =
            images[((size_t)(b * 2 + c) * SLEN + (i0 + y)) * SLEN + (j0 + x)];
    }
    __syncthreads();

    // ---- conv1 (FFMA): one pixel per thread, 20 oc ----
    {
        float v[2][9];
        #pragma unroll
        for (int c = 0; c < 2; c++)
            #pragma unroll
            for (int dy = 0; dy < 3; dy++)
                #pragma unroll
                for (int dx = 0; dx < 3; dx++)
                    v[c][dy * 3 + dx] = sIn[(lp * 2 + c) * 100 + (y + dy) * 10 + (x + dx)];
        #pragma unroll 5
        for (int oc = 0; oc < 20; oc++) {
            float acc = sB1[oc];
            #pragma unroll
            for (int c = 0; c < 2; c++) {
                const float* w = &sW1[(oc * 2 + c) * 12];
                float4 w0 = *(const float4*)(w);
                float4 w4 = *(const float4*)(w + 4);
                float  w8 = w[8];
                acc += v[c][0]*w0.x + v[c][1]*w0.y + v[c][2]*w0.z + v[c][3]*w0.w
                     + v[c][4]*w4.x + v[c][5]*w4.y + v[c][6]*w4.z + v[c][7]*w4.w
                     + v[c][8]*w8;
            }
            // padded tile, ic-stride 104, rna tf32 (mma operand)
            sH1[lp * 2496 + oc * 104 + (y + 1) * 10 + (x + 1)] =
                to_tf32(fmaxf(acc, 0.f));
        }
    }
    __syncthreads();

    // ---- conv2 via mma.sync: warp wid owns 32 rows (pixels) of one patch ----
    const int lane = tid & 31;
    const int wid  = tid >> 5;
    const int lp_w = wid >> 1;          // patch for this warp
    const int half = wid & 1;           // pixel half: 0 -> 0..31, 1 -> 32..63
    const int g    = lane >> 2;         // 0..7
    const int tig  = lane & 3;          // 0..3

    float acc[2][3][4];
    #pragma unroll
    for (int mt = 0; mt < 2; mt++)
        #pragma unroll
        for (int nt = 0; nt < 3; nt++)
            #pragma unroll
            for (int q = 0; q < 4; q++) acc[mt][nt][q] = 0.f;

    const float* h1b = sH1 + lp_w * 2496;

    for (int tap = 0; tap < 9; tap++) {
        const int dy = tap / 3, dx = tap - 3 * dy;
        const int shift = dy * 10 + dx + g;     // + (x+dx) with x=g
        #pragma unroll
        for (int kc = 0; kc < 3; kc++) {
            const int ic0 = kc * 8 + tig;
            uint32_t a[2][4];
            #pragma unroll
            for (int mt = 0; mt < 2; mt++) {
                const int yy = half * 4 + mt * 2;       // base y of m16 tile
                const float* base = h1b + ic0 * 104 + yy * 10 + shift;
                a[mt][0] = F2U(base[0]);
                a[mt][1] = F2U(base[10]);
                a[mt][2] = F2U(base[4 * 104]);
                a[mt][3] = F2U(base[4 * 104 + 10]);
            }
            const float* wb = sW2 + tap * 600 + kc * 8 + tig;
            #pragma unroll
            for (int nt = 0; nt < 3; nt++) {
                uint32_t b0 = F2U(wb[(nt * 8 + g) * 25]);
                uint32_t b1 = F2U(wb[(nt * 8 + g) * 25 + 4]);
                mma_tf32(acc[0][nt], a[0][0], a[0][1], a[0][2], a[0][3], b0, b1);
                mma_tf32(acc[1][nt], a[1][0], a[1][1], a[1][2], a[1][3], b0, b1);
            }
        }
    }
    __syncthreads();   // all reads of sH1 done; safe to reuse as staging

    // ---- epilogue: bias+relu -> stage [lp][oc][65] (reusing sH1) ----
    float* stg = sH1 + lp_w * 2496;
    #pragma unroll
    for (int mt = 0; mt < 2; mt++) {
        const int row = half * 32 + mt * 16 + g;
        #pragma unroll
        for (int nt = 0; nt < 3; nt++) {
            const int col = nt * 8 + tig * 2;
            if (col < 20) {
                stg[col * 65 + row]     = fmaxf(acc[mt][nt][0] + sB2[col], 0.f);
                stg[col * 65 + row + 8] = fmaxf(acc[mt][nt][2] + sB2[col], 0.f);
            }
            if (col + 1 < 20) {
                stg[(col + 1) * 65 + row]     = fmaxf(acc[mt][nt][1] + sB2[col + 1], 0.f);
                stg[(col + 1) * 65 + row + 8] = fmaxf(acc[mt][nt][3] + sB2[col + 1], 0.f);
            }
        }
    }
    __syncthreads();

    // ---- coalesced write to g_h2: [patch][oc*64 + pix] ----
    {
        float* dst = &g_h2[(size_t)patch * 1280 + pix];
        const float* src = sH1 + lp * 2496 + pix;
        #pragma unroll 5
        for (int oc = 0; oc < 20; oc++)
            dst[oc * 64] = src[oc * 65];
    }
}

// ===========================================================================
// Kernel 2 (unchanged from R3): fused MLP on mma.sync tf32
// ===========================================================================
#define LDACT 260
#define LDB   36
#define SACT 0
#define SB   33280
#define SAF  (33280 + 9216)
#define SMEM_FLOATS (33280 + 9216 + 4608)

__global__ __launch_bounds__(512, 1) void mlp_mma_kernel(
    const float* __restrict__ fc1_w, const float* __restrict__ fc1_b,
    const float* __restrict__ fc2_w, const float* __restrict__ fc2_b,
    const float* __restrict__ fc3_w, const float* __restrict__ fc3_b,
    const float* __restrict__ fcf_w, const float* __restrict__ fcf_b,
    float* __restrict__ out)
{
    extern __shared__ __align__(16) float sm[];
    float* sAct = sm + SACT;
    float* sB   = sm + SB;
    float* sA   = sm + SAF;

    const int tid  = threadIdx.x;
    const int lane = tid & 31;
    const int wid  = tid >> 5;
    const int wm   = wid >> 2;
    const int wn   = wid & 3;
    const int g    = lane >> 2;
    const int tig  = lane & 3;
    const int m0   = blockIdx.x * 128;

    const int sr = tid >> 3, sf = tid & 7;

    float acc[2][8][4];
    float4 bst[4];
    float4 ast[2];

    // =============== fc1: K=1280, A streamed from g_h2 ===============
    {
        const int NC = 40;
        #pragma unroll
        for (int mt = 0; mt < 2; mt++)
            #pragma unroll
            for (int nt = 0; nt < 8; nt++)
                #pragma unroll
                for (int q = 0; q < 4; q++) acc[mt][nt][q] = 0.f;

        #pragma unroll
        for (int p = 0; p < 4; p++)
            bst[p] = *(const float4*)&fc1_w[(size_t)(sr + p * 64) * 1280 + sf * 4];
        #pragma unroll
        for (int p = 0; p < 2; p++)
            ast[p] = *(const float4*)&g_h2[(size_t)(m0 + sr + p * 64) * 1280 + sf * 4];

        for (int c = 0; c < NC; c++) {
            __syncthreads();
            #pragma unroll
            for (int p = 0; p < 4; p++) {
                float4 v = bst[p];
                v.x = to_tf32(v.x); v.y = to_tf32(v.y);
                v.z = to_tf32(v.z); v.w = to_tf32(v.w);
                *(float4*)&sB[(sr + p * 64) * LDB + sf * 4] = v;
            }
            #pragma unroll
            for (int p = 0; p < 2; p++) {
                float4 v = ast[p];
                v.x = to_tf32(v.x); v.y = to_tf32(v.y);
                v.z = to_tf32(v.z); v.w = to_tf32(v.w);
                *(float4*)&sA[(sr + p * 64) * LDB + sf * 4] = v;
            }
            __syncthreads();
            if (c + 1 < NC) {
                const int k0 = (c + 1) * 32;
                #pragma unroll
                for (int p = 0; p < 4; p++)
                    bst[p] = *(const float4*)&fc1_w[(size_t)(sr + p * 64) * 1280 + k0 + sf * 4];
                #pragma unroll
                for (int p = 0; p < 2; p++)
                    ast[p] = *(const float4*)&g_h2[(size_t)(m0 + sr + p * 64) * 1280 + k0 + sf * 4];
            }
            #pragma unroll
            for (int k8 = 0; k8 < 4; k8++) {
                const int kk = k8 * 8;
                uint32_t a[2][4];
                #pragma unroll
                for (int mt = 0; mt < 2; mt++) {
                    const int r = (wm * 32 + mt * 16 + g) * LDB + kk + tig;
                    a[mt][0] = F2U(sA[r]);
                    a[mt][1] = F2U(sA[r + 8 * LDB]);
                    a[mt][2] = F2U(sA[r + 4]);
                    a[mt][3] = F2U(sA[r + 8 * LDB + 4]);
                }
                #pragma unroll
                for (int nt = 0; nt < 8; nt++) {
                    const int nb = (wn * 64 + nt * 8 + g) * LDB + kk + tig;
                    uint32_t b0 = F2U(sB[nb]);
                    uint32_t b1 = F2U(sB[nb + 4]);
                    mma_tf32(acc[0][nt], a[0][0], a[0][1], a[0][2], a[0][3], b0, b1);
                    mma_tf32(acc[1][nt], a[1][0], a[1][1], a[1][2], a[1][3], b0, b1);
                }
            }
        }
        __syncthreads();
        #pragma unroll
        for (int mt = 0; mt < 2; mt++)
            #pragma unroll
            for (int nt = 0; nt < 8; nt++) {
                const int row = wm * 32 + mt * 16 + g;
                const int col = wn * 64 + nt * 8 + tig * 2;
                const float bv0 = fc1_b[col], bv1 = fc1_b[col + 1];
                sAct[row * LDACT + col]           = to_tf32(fmaxf(acc[mt][nt][0] + bv0, 0.f));
                sAct[row * LDACT + col + 1]       = to_tf32(fmaxf(acc[mt][nt][1] + bv1, 0.f));
                sAct[(row + 8) * LDACT + col]     = to_tf32(fmaxf(acc[mt][nt][2] + bv0, 0.f));
                sAct[(row + 8) * LDACT + col + 1] = to_tf32(fmaxf(acc[mt][nt][3] + bv1, 0.f));
            }
        __syncthreads();
    }

    // =============== fc2 & fc3 ===============
    for (int layer = 0; layer < 2; layer++) {
        const float* wg = layer ? fc3_w : fc2_w;
        const float* bg = layer ? fc3_b : fc2_b;
        const int NC = 8;
        #pragma unroll
        for (int mt = 0; mt < 2; mt++)
            #pragma unroll
            for (int nt = 0; nt < 8; nt++)
                #pragma unroll
                for (int q = 0; q < 4; q++) acc[mt][nt][q] = 0.f;

        #pragma unroll
        for (int p = 0; p < 4; p++)
            bst[p] = *(const float4*)&wg[(size_t)(sr + p * 64) * 256 + sf * 4];

        for (int c = 0; c < NC; c++) {
            __syncthreads();
            #pragma unroll
            for (int p = 0; p < 4; p++) {
                float4 v = bst[p];
                v.x = to_tf32(v.x); v.y = to_tf32(v.y);
                v.z = to_tf32(v.z); v.w = to_tf32(v.w);
                *(float4*)&sB[(sr + p * 64) * LDB + sf * 4] = v;
            }
            __syncthreads();
            if (c + 1 < NC) {
                const int k0 = (c + 1) * 32;
                #pragma unroll
                for (int p = 0; p < 4; p++)
                    bst[p] = *(const float4*)&wg[(size_t)(sr + p * 64) * 256 + k0 + sf * 4];
            }
            const int cb = c * 32;
            #pragma unroll
            for (int k8 = 0; k8 < 4; k8++) {
                const int kk = cb + k8 * 8;
                uint32_t a[2][4];
                #pragma unroll
                for (int mt = 0; mt < 2; mt++) {
                    const int r = (wm * 32 + mt * 16 + g) * LDACT + kk + tig;
                    a[mt][0] = F2U(sAct[r]);
                    a[mt][1] = F2U(sAct[r + 8 * LDACT]);
                    a[mt][2] = F2U(sAct[r + 4]);
                    a[mt][3] = F2U(sAct[r + 8 * LDACT + 4]);
                }
                #pragma unroll
                for (int nt = 0; nt < 8; nt++) {
                    const int nb = (wn * 64 + nt * 8 + g) * LDB + (k8 * 8) + tig;
                    uint32_t b0 = F2U(sB[nb]);
                    uint32_t b1 = F2U(sB[nb + 4]);
                    mma_tf32(acc[0][nt], a[0][0], a[0][1], a[0][2], a[0][3], b0, b1);
                    mma_tf32(acc[1][nt], a[1][0], a[1][1], a[1][2], a[1][3], b0, b1);
                }
            }
        }
        __syncthreads();
        #pragma unroll
        for (int mt = 0; mt < 2; mt++)
            #pragma unroll
            for (int nt = 0; nt < 8; nt++) {
                const int row = wm * 32 + mt * 16 + g;
                const int col = wn * 64 + nt * 8 + tig * 2;
                const float bv0 = bg[col], bv1 = bg[col + 1];
                sAct[row * LDACT + col]           = to_tf32(fmaxf(acc[mt][nt][0] + bv0, 0.f));
                sAct[row * LDACT + col + 1]       = to_tf32(fmaxf(acc[mt][nt][1] + bv1, 0.f));
                sAct[(row + 8) * LDACT + col]     = to_tf32(fmaxf(acc[mt][nt][2] + bv0, 0.f));
                sAct[(row + 8) * LDACT + col + 1] = to_tf32(fmaxf(acc[mt][nt][3] + bv1, 0.f));
            }
        __syncthreads();
    }

    // =============== fcf: K=256, N=27 ===============
    {
        #pragma unroll
        for (int mt = 0; mt < 2; mt++)
            #pragma unroll
            for (int q = 0; q < 4; q++) acc[mt][0][q] = 0.f;

        for (int i = tid; i < 32 * 64; i += 512) {
            int r = i >> 6, f = i & 63;
            float4 v = make_float4(0.f, 0.f, 0.f, 0.f);
            if (r < 27) v = *(const float4*)&fcf_w[(size_t)r * 256 + f * 4];
            v.x = to_tf32(v.x); v.y = to_tf32(v.y);
            v.z = to_tf32(v.z); v.w = to_tf32(v.w);
            *(float4*)&sB[r * LDACT + f * 4] = v;
        }
        __syncthreads();

        #pragma unroll 4
        for (int k8 = 0; k8 < 32; k8++) {
            const int kk = k8 * 8;
            uint32_t a[2][4];
            #pragma unroll
            for (int mt = 0; mt < 2; mt++) {
                const int r = (wm * 32 + mt * 16 + g) * LDACT + kk + tig;
                a[mt][0] = F2U(sAct[r]);
                a[mt][1] = F2U(sAct[r + 8 * LDACT]);
                a[mt][2] = F2U(sAct[r + 4]);
                a[mt][3] = F2U(sAct[r + 8 * LDACT + 4]);
            }
            const int nb = (wn * 8 + g) * LDACT + kk + tig;
            uint32_t b0 = F2U(sB[nb]);
            uint32_t b1 = F2U(sB[nb + 4]);
            mma_tf32(acc[0][0], a[0][0], a[0][1], a[0][2], a[0][3], b0, b1);
            mma_tf32(acc[1][0], a[1][0], a[1][1], a[1][2], a[1][3], b0, b1);
        }

        #pragma unroll
        for (int mt = 0; mt < 2; mt++) {
            const int row = m0 + wm * 32 + mt * 16 + g;
            const int col = wn * 8 + tig * 2;
            #pragma unroll
            for (int h = 0; h < 2; h++) {
                const int rr = row + h * 8;
                if (rr < NP) {
                    if (col < 27)
                        out[(size_t)rr * 27 + col] = acc[mt][0][h * 2 + 0] + fcf_b[col];
                    if (col + 1 < 27)
                        out[(size_t)rr * 27 + col + 1] = acc[mt][0][h * 2 + 1] + fcf_b[col + 1];
                }
            }
        }
    }
}

// ---------------------------------------------------------------------------
extern "C" void kernel_launch(void* const* d_in, const int* in_sizes, int n_in,
                              void* d_out, int out_size)
{
    const float* images  = (const float*)d_in[0];
    const float* conv1_w = (const float*)d_in[1];
    const float* conv1_b = (const float*)d_in[2];
    const float* conv2_w = (const float*)d_in[3];
    const float* conv2_b = (const float*)d_in[4];
    const float* fc1_w   = (const float*)d_in[5];
    const float* fc1_b   = (const float*)d_in[6];
    const float* fc2_w   = (const float*)d_in[7];
    const float* fc2_b   = (const float*)d_in[8];
    const float* fc3_w   = (const float*)d_in[9];
    const float* fc3_b   = (const float*)d_in[10];
    const float* fcf_w   = (const float*)d_in[11];
    const float* fcf_b   = (const float*)d_in[12];
    float* out = (float*)d_out;

    const size_t smem1 = C_SMEM_FLOATS * sizeof(float);   // 109,968 B
    cudaFuncSetAttribute(conv_mma_kernel,
                         cudaFuncAttributeMaxDynamicSharedMemorySize, (int)smem1);
    conv_mma_kernel<<<NP / 8, 512, smem1>>>(images, conv1_w, conv1_b, conv2_w, conv2_b);

    const size_t smem2 = SMEM_FLOATS * sizeof(float);     // 188,416 B
    cudaFuncSetAttribute(mlp_mma_kernel,
                         cudaFuncAttributeMaxDynamicSharedMemorySize, (int)smem2);
    mlp_mma_kernel<<<MROWS_PAD / 128, 512, smem2>>>(
        fc1_w, fc1_b, fc2_w, fc2_b, fc3_w, fc3_b, fcf_w, fcf_b, out);
}

// round 7
// speedup vs baseline: 3.9215x; 1.1294x over previous
#include <cuda_runtime.h>
#include <cuda_fp16.h>
#include <cstdint>

#define NP 76832          // 32 * 49 * 49 patches
#define HN 49
#define SLEN 104
#define MROWS_PAD 76928   // 601 * 128

// conv output scratch, fp16 (zero-initialized device global; pad rows stay zero)
__device__ __half g_h2[(size_t)MROWS_PAD * 1280];

// ---------------------------------------------------------------------------
__device__ __forceinline__ uint32_t s2u(const void* p) {
    return (uint32_t)__cvta_generic_to_shared(p);
}
__device__ __forceinline__ void ldsm4(uint32_t* r, uint32_t addr) {
    asm volatile("ldmatrix.sync.aligned.m8n8.x4.shared.b16 {%0,%1,%2,%3}, [%4];"
        : "=r"(r[0]), "=r"(r[1]), "=r"(r[2]), "=r"(r[3]) : "r"(addr));
}
__device__ __forceinline__ void ldsm2(uint32_t* r, uint32_t addr) {
    asm volatile("ldmatrix.sync.aligned.m8n8.x2.shared.b16 {%0,%1}, [%2];"
        : "=r"(r[0]), "=r"(r[1]) : "r"(addr));
}
__device__ __forceinline__ void mma_f16(float* c, const uint32_t* a,
                                        uint32_t b0, uint32_t b1) {
    asm volatile(
        "mma.sync.aligned.m16n8k16.row.col.f32.f16.f16.f32 "
        "{%0,%1,%2,%3}, {%4,%5,%6,%7}, {%8,%9}, {%0,%1,%2,%3};"
        : "+f"(c[0]), "+f"(c[1]), "+f"(c[2]), "+f"(c[3])
        : "r"(a[0]), "r"(a[1]), "r"(a[2]), "r"(a[3]), "r"(b0), "r"(b1));
}
__device__ __forceinline__ uint32_t pack_h2(float a, float b) {
    __half2 h = __floats2half2_rn(a, b);
    return *(uint32_t*)&h;
}

// ===========================================================================
// Kernel 1: conv1 (FFMA f32) + conv2 (mma.sync fp16 via ldmatrix)
// 8 patches / CTA, 512 threads = 16 warps (2 warps per patch).
// ===========================================================================
// smem byte offsets
#define CV_H1   0          // 8 lp x 100 rows x 40 halves = 64000 B (k=ic pad 40)
#define CV_W2   64000      // 9 taps x 24 n x 40 halves   = 17280 B
#define CV_IN   81280      // 8 x 2 x 100 f32             = 6400 B
#define CV_W1   87680      // 480 f32                     = 1920 B
#define CV_B1   89600      // 20 f32
#define CV_B2   89680      // 24 f32
#define CV_SMEM 89776

__global__ __launch_bounds__(512, 1) void conv_mma_kernel(
    const float* __restrict__ images,
    const float* __restrict__ w1, const float* __restrict__ b1,
    const float* __restrict__ w2, const float* __restrict__ b2)
{
    extern __shared__ __align__(16) char smc[];
    __half* sH1 = (__half*)(smc + CV_H1);
    __half* sW2 = (__half*)(smc + CV_W2);
    float*  sIn = (float*)(smc + CV_IN);
    float*  sW1 = (float*)(smc + CV_W1);
    float*  sB1 = (float*)(smc + CV_B1);
    float*  sB2 = (float*)(smc + CV_B2);

    const int tid = threadIdx.x;

    // zero-fill sH1 + sW2 (contiguous) and sIn
    {
        uint32_t* z = (uint32_t*)smc;
        for (int i = tid; i < (64000 + 17280) / 4; i += 512) z[i] = 0u;
        for (int i = tid; i < 1600; i += 512) sIn[i] = 0.f;
    }
    // stage conv1 weights
    for (int i = tid; i < 20 * 2 * 9; i += 512) {
        int oc = i / 18, r = i % 18, ic = r / 9, t = r % 9;
        sW1[(oc * 2 + ic) * 12 + t] = w1[i];
    }
    if (tid < 20) sB1[tid] = b1[tid];
    if (tid < 24) sB2[tid] = (tid < 20) ? b2[tid] : 0.f;
    __syncthreads();

    // scatter conv2 weights: [tap][n=oc][k=ic] halves, stride 40
    for (int i = tid; i < 20 * 180; i += 512) {
        int oc = i / 180, r = i % 180, ic = r / 9, tap = r % 9;
        sW2[tap * 960 + oc * 40 + ic] = __float2half(w2[i]);
    }

    // load input patches (interior of padded 10x10)
    const int lp  = tid >> 6;
    const int pix = tid & 63;
    const int y = pix >> 3, x = pix & 7;
    const int patch = blockIdx.x * 8 + lp;
    const int b  = patch / (HN * HN);
    const int t2 = patch % (HN * HN);
    const int i0 = (t2 / HN) * 2, j0 = (t2 % HN) * 2;
    #pragma unroll
    for (int c = 0; c < 2; c++) {
        sIn[(lp * 2 + c) * 100 + (y + 1) * 10 + (x + 1)] =
            images[((size_t)(b * 2 + c) * SLEN + (i0 + y)) * SLEN + (j0 + x)];
    }
    __syncthreads();

    // ---- conv1: one pixel per thread; pack oc pairs into half2 ----
    {
        float v[2][9];
        #pragma unroll
        for (int c = 0; c < 2; c++)
            #pragma unroll
            for (int dy = 0; dy < 3; dy++)
                #pragma unroll
                for (int dx = 0; dx < 3; dx++)
                    v[c][dy * 3 + dx] = sIn[(lp * 2 + c) * 100 + (y + dy) * 10 + (x + dx)];
        const int rr = (y + 1) * 10 + (x + 1);
        #pragma unroll
        for (int ocp = 0; ocp < 10; ocp++) {
            float acc0 = sB1[2 * ocp], acc1 = sB1[2 * ocp + 1];
            #pragma unroll
            for (int c = 0; c < 2; c++) {
                const float* wa = &sW1[((2 * ocp) * 2 + c) * 12];
                const float* wb = &sW1[((2 * ocp + 1) * 2 + c) * 12];
                #pragma unroll
                for (int t = 0; t < 9; t++) {
                    acc0 += v[c][t] * wa[t];
                    acc1 += v[c][t] * wb[t];
                }
            }
            *(uint32_t*)&sH1[lp * 4000 + rr * 40 + 2 * ocp] =
                pack_h2(fmaxf(acc0, 0.f), fmaxf(acc1, 0.f));
        }
    }
    __syncthreads();

    // ---- conv2 via fp16 mma + ldmatrix ----
    const int l    = tid & 31;
    const int wid  = tid >> 5;
    const int lp_w = wid >> 1;
    const int hf   = wid & 1;
    const int g    = l >> 2;
    const int tig  = l & 3;

    const uint32_t sH1u = s2u(sH1 + lp_w * 4000);
    const uint32_t sW2u = s2u(sW2);

    const int l16 = l & 15, lg = l >> 4;
    const int pA0 = hf * 32 + l16;
    const int pA1 = pA0 + 16;
    const int rA0 = (pA0 >> 3) * 10 + (pA0 & 7);
    const int rA1 = (pA1 >> 3) * 10 + (pA1 & 7);
    const uint32_t aB0 = sH1u + (uint32_t)(rA0 * 40 + lg * 8) * 2;
    const uint32_t aB1 = sH1u + (uint32_t)(rA1 * 40 + lg * 8) * 2;

    const int bt   = l >> 3;
    const int bn01 = (bt >> 1) * 8 + (l & 7);
    const int bk01 = (bt & 1) * 8;
    const uint32_t bB01 = sW2u + (uint32_t)(bn01 * 40 + bk01) * 2;
    const int l2  = l & 15;
    const int bn2 = 16 + (l2 & 7);
    const int bk2 = ((l2 >> 3) & 1) * 8;
    const uint32_t bB2 = sW2u + (uint32_t)(bn2 * 40 + bk2) * 2;

    float acc[2][3][4];
    #pragma unroll
    for (int mt = 0; mt < 2; mt++)
        #pragma unroll
        for (int nt = 0; nt < 3; nt++)
            #pragma unroll
            for (int q = 0; q < 4; q++) acc[mt][nt][q] = 0.f;

    #pragma unroll
    for (int tap = 0; tap < 9; tap++) {
        const int dy = tap / 3, dx = tap % 3;
        const uint32_t ro = (uint32_t)((dy * 10 + dx) * 40) * 2;
        const uint32_t wo = (uint32_t)(tap * 960) * 2;
        #pragma unroll
        for (int c = 0; c < 2; c++) {
            const uint32_t ko = (uint32_t)(c * 16) * 2;
            uint32_t a0[4], a1[4], b01[4], b2[2];
            ldsm4(a0, aB0 + ro + ko);
            ldsm4(a1, aB1 + ro + ko);
            ldsm4(b01, bB01 + wo + ko);
            ldsm2(b2, bB2 + wo + ko);
            mma_f16(acc[0][0], a0, b01[0], b01[1]);
            mma_f16(acc[0][1], a0, b01[2], b01[3]);
            mma_f16(acc[0][2], a0, b2[0],  b2[1]);
            mma_f16(acc[1][0], a1, b01[0], b01[1]);
            mma_f16(acc[1][1], a1, b01[2], b01[3]);
            mma_f16(acc[1][2], a1, b2[0],  b2[1]);
        }
    }
    __syncthreads();   // conv2 reads of sH1 done; reuse region as f32 staging

    // ---- epilogue: bias+relu -> stage f32 [lp][oc][65] over sH1 region ----
    float* stg = (float*)smc;                 // 8*20*65*4 = 41600 B <= 64000
    float* stw = stg + lp_w * 1300;
    #pragma unroll
    for (int mt = 0; mt < 2; mt++) {
        const int row = hf * 32 + mt * 16 + g;
        #pragma unroll
        for (int nt = 0; nt < 3; nt++) {
            const int col = nt * 8 + tig * 2;
            if (col < 20) {
                stw[col * 65 + row]     = fmaxf(acc[mt][nt][0] + sB2[col], 0.f);
                stw[col * 65 + row + 8] = fmaxf(acc[mt][nt][2] + sB2[col], 0.f);
            }
            if (col + 1 < 20) {
                stw[(col + 1) * 65 + row]     = fmaxf(acc[mt][nt][1] + sB2[col + 1], 0.f);
                stw[(col + 1) * 65 + row + 8] = fmaxf(acc[mt][nt][3] + sB2[col + 1], 0.f);
            }
        }
    }
    __syncthreads();

    // ---- coalesced fp16 write to g_h2 ----
    for (int i = tid; i < 8 * 20 * 32; i += 512) {
        const int lp2 = i / 640, r = i % 640, oc = r >> 5, pp = r & 31;
        const float* s = stg + lp2 * 1300 + oc * 65;
        const int patch2 = blockIdx.x * 8 + lp2;
        ((uint32_t*)(g_h2 + (size_t)patch2 * 1280 + oc * 64))[pp] =
            pack_h2(s[2 * pp], s[2 * pp + 1]);
    }
}

// ===========================================================================
// Kernel 2: fused MLP on fp16 mma + ldmatrix. CTA: M=128, N=256, 16 warps 4x4.
// ===========================================================================
// smem byte offsets
#define ML_ACT  0          // 128 x 264 halves = 67584 B (stride 264)
#define ML_B    67584      // 256 x 40 halves  = 20480 B (chunk k32, stride 40)
#define ML_A    88064      // 128 x 40 halves  = 10240 B
#define ML_SMEM 98304

__global__ __launch_bounds__(512, 1) void mlp_mma_kernel(
    const float* __restrict__ fc1_w, const float* __restrict__ fc1_b,
    const float* __restrict__ fc2_w, const float* __restrict__ fc2_b,
    const float* __restrict__ fc3_w, const float* __restrict__ fc3_b,
    const float* __restrict__ fcf_w, const float* __restrict__ fcf_b,
    float* __restrict__ out)
{
    extern __shared__ __align__(16) char smc[];
    __half* sAct = (__half*)(smc + ML_ACT);
    __half* sB   = (__half*)(smc + ML_B);
    __half* sA   = (__half*)(smc + ML_A);

    const int tid  = threadIdx.x;
    const int l    = tid & 31;
    const int wid  = tid >> 5;
    const int wm   = wid >> 2;
    const int wn   = wid & 3;
    const int g    = l >> 2;
    const int tig  = l & 3;
    const int m0   = blockIdx.x * 128;

    const uint32_t sActu = s2u(sAct);
    const uint32_t sBu   = s2u(sB);
    const uint32_t sAu   = s2u(sA);

    // ldmatrix lane geometry
    const int l16 = l & 15, lg = l >> 4;
    // A from sA (stride 40): fc1
    const uint32_t aA0 = sAu + (uint32_t)((wm * 32 + l16) * 40 + lg * 8) * 2;
    const uint32_t aA1 = aA0 + 16 * 40 * 2;
    // A from sAct (stride 264): fc2/3/fcf
    const uint32_t cA0 = sActu + (uint32_t)((wm * 32 + l16) * 264 + lg * 8) * 2;
    const uint32_t cA1 = cA0 + 16 * 264 * 2;
    // B from sB (stride 40): per n16 group
    const int bt = l >> 3;
    const int bnl = (bt >> 1) * 8 + (l & 7);
    const int bkl = (bt & 1) * 8;
    uint32_t bG[4];
    #pragma unroll
    for (int gn = 0; gn < 4; gn++)
        bG[gn] = sBu + (uint32_t)((wn * 64 + gn * 16 + bnl) * 40 + bkl) * 2;

    // staging thread mapping
    const int rB = tid >> 1, ofB = (tid & 1) * 16;      // B: row, 16-f32 offset
    const int rA = tid >> 2, qA = tid & 3;              // A: row, 16-byte quad

    float acc[2][8][4];
    float4 bq[4];
    uint4  aq;

    // ================= fc1: K=1280 (40 chunks of 32) =================
    {
        #pragma unroll
        for (int mt = 0; mt < 2; mt++)
            #pragma unroll
            for (int nt = 0; nt < 8; nt++)
                #pragma unroll
                for (int q = 0; q < 4; q++) acc[mt][nt][q] = 0.f;

        #pragma unroll
        for (int p = 0; p < 4; p++)
            bq[p] = *(const float4*)&fc1_w[(size_t)rB * 1280 + ofB + p * 4];
        aq = *(const uint4*)((const __half*)g_h2 + (size_t)(m0 + rA) * 1280 + qA * 8);

        for (int c = 0; c < 40; c++) {
            __syncthreads();
            {
                uint4 u0, u1;
                u0.x = pack_h2(bq[0].x, bq[0].y); u0.y = pack_h2(bq[0].z, bq[0].w);
                u0.z = pack_h2(bq[1].x, bq[1].y); u0.w = pack_h2(bq[1].z, bq[1].w);
                u1.x = pack_h2(bq[2].x, bq[2].y); u1.y = pack_h2(bq[2].z, bq[2].w);
                u1.z = pack_h2(bq[3].x, bq[3].y); u1.w = pack_h2(bq[3].z, bq[3].w);
                *(uint4*)&sB[rB * 40 + ofB]     = u0;
                *(uint4*)&sB[rB * 40 + ofB + 8] = u1;
                *(uint4*)&sA[rA * 40 + qA * 8]  = aq;
            }
            __syncthreads();
            if (c + 1 < 40) {
                const int k0 = (c + 1) * 32;
                #pragma unroll
                for (int p = 0; p < 4; p++)
                    bq[p] = *(const float4*)&fc1_w[(size_t)rB * 1280 + k0 + ofB + p * 4];
                aq = *(const uint4*)((const __half*)g_h2 +
                        (size_t)(m0 + rA) * 1280 + k0 + qA * 8);
            }
            #pragma unroll
            for (int kk = 0; kk < 32; kk += 16) {
                uint32_t a0[4], a1[4];
                ldsm4(a0, aA0 + kk * 2);
                ldsm4(a1, aA1 + kk * 2);
                #pragma unroll
                for (int gn = 0; gn < 4; gn++) {
                    uint32_t bb[4];
                    ldsm4(bb, bG[gn] + kk * 2);
                    mma_f16(acc[0][2 * gn],     a0, bb[0], bb[1]);
                    mma_f16(acc[0][2 * gn + 1], a0, bb[2], bb[3]);
                    mma_f16(acc[1][2 * gn],     a1, bb[0], bb[1]);
                    mma_f16(acc[1][2 * gn + 1], a1, bb[2], bb[3]);
                }
            }
        }
        __syncthreads();
        #pragma unroll
        for (int mt = 0; mt < 2; mt++)
            #pragma unroll
            for (int nt = 0; nt < 8; nt++) {
                const int row = wm * 32 + mt * 16 + g;
                const int col = wn * 64 + nt * 8 + tig * 2;
                const float b0 = fc1_b[col], b1 = fc1_b[col + 1];
                *(uint32_t*)&sAct[row * 264 + col] =
                    pack_h2(fmaxf(acc[mt][nt][0] + b0, 0.f),
                            fmaxf(acc[mt][nt][1] + b1, 0.f));
                *(uint32_t*)&sAct[(row + 8) * 264 + col] =
                    pack_h2(fmaxf(acc[mt][nt][2] + b0, 0.f),
                            fmaxf(acc[mt][nt][3] + b1, 0.f));
            }
        __syncthreads();
    }

    // ================= fc2 & fc3: K=256 (8 chunks of 32) =================
    for (int layer = 0; layer < 2; layer++) {
        const float* wg = layer ? fc3_w : fc2_w;
        const float* bg = layer ? fc3_b : fc2_b;
        #pragma unroll
        for (int mt = 0; mt < 2; mt++)
            #pragma unroll
            for (int nt = 0; nt < 8; nt++)
                #pragma unroll
                for (int q = 0; q < 4; q++) acc[mt][nt][q] = 0.f;

        #pragma unroll
        for (int p = 0; p < 4; p++)
            bq[p] = *(const float4*)&wg[(size_t)rB * 256 + ofB + p * 4];

        for (int c = 0; c < 8; c++) {
            __syncthreads();
            {
                uint4 u0, u1;
                u0.x = pack_h2(bq[0].x, bq[0].y); u0.y = pack_h2(bq[0].z, bq[0].w);
                u0.z = pack_h2(bq[1].x, bq[1].y); u0.w = pack_h2(bq[1].z, bq[1].w);
                u1.x = pack_h2(bq[2].x, bq[2].y); u1.y = pack_h2(bq[2].z, bq[2].w);
                u1.z = pack_h2(bq[3].x, bq[3].y); u1.w = pack_h2(bq[3].z, bq[3].w);
                *(uint4*)&sB[rB * 40 + ofB]     = u0;
                *(uint4*)&sB[rB * 40 + ofB + 8] = u1;
            }
            __syncthreads();
            if (c + 1 < 8) {
                const int k0 = (c + 1) * 32;
                #pragma unroll
                for (int p = 0; p < 4; p++)
                    bq[p] = *(const float4*)&wg[(size_t)rB * 256 + k0 + ofB + p * 4];
            }
            #pragma unroll
            for (int kk = 0; kk < 32; kk += 16) {
                const int kg = c * 32 + kk;
                uint32_t a0[4], a1[4];
                ldsm4(a0, cA0 + kg * 2);
                ldsm4(a1, cA1 + kg * 2);
                #pragma unroll
                for (int gn = 0; gn < 4; gn++) {
                    uint32_t bb[4];
                    ldsm4(bb, bG[gn] + kk * 2);
                    mma_f16(acc[0][2 * gn],     a0, bb[0], bb[1]);
                    mma_f16(acc[0][2 * gn + 1], a0, bb[2], bb[3]);
                    mma_f16(acc[1][2 * gn],     a1, bb[0], bb[1]);
                    mma_f16(acc[1][2 * gn + 1], a1, bb[2], bb[3]);
                }
            }
        }
        __syncthreads();
        #pragma unroll
        for (int mt = 0; mt < 2; mt++)
            #pragma unroll
            for (int nt = 0; nt < 8; nt++) {
                const int row = wm * 32 + mt * 16 + g;
                const int col = wn * 64 + nt * 8 + tig * 2;
                const float b0 = bg[col], b1 = bg[col + 1];
                *(uint32_t*)&sAct[row * 264 + col] =
                    pack_h2(fmaxf(acc[mt][nt][0] + b0, 0.f),
                            fmaxf(acc[mt][nt][1] + b1, 0.f));
                *(uint32_t*)&sAct[(row + 8) * 264 + col] =
                    pack_h2(fmaxf(acc[mt][nt][2] + b0, 0.f),
                            fmaxf(acc[mt][nt][3] + b1, 0.f));
            }
        __syncthreads();
    }

    // ================= fcf: K=256, N=27 (pad 32) =================
    {
        // stage fcf_w as [32 n][264 halves] over sB region (16896 B <= 20480)
        const int rF = tid >> 4, ofF = (tid & 15) * 16;
        {
            float4 f[4];
            #pragma unroll
            for (int p = 0; p < 4; p++)
                f[p] = (rF < 27)
                     ? *(const float4*)&fcf_w[(size_t)rF * 256 + ofF + p * 4]
                     : make_float4(0.f, 0.f, 0.f, 0.f);
            uint4 u0, u1;
            u0.x = pack_h2(f[0].x, f[0].y); u0.y = pack_h2(f[0].z, f[0].w);
            u0.z = pack_h2(f[1].x, f[1].y); u0.w = pack_h2(f[1].z, f[1].w);
            u1.x = pack_h2(f[2].x, f[2].y); u1.y = pack_h2(f[2].z, f[2].w);
            u1.z = pack_h2(f[3].x, f[3].y); u1.w = pack_h2(f[3].z, f[3].w);
            *(uint4*)&sB[rF * 264 + ofF]     = u0;
            *(uint4*)&sB[rF * 264 + ofF + 8] = u1;
        }
        __syncthreads();

        const int l2 = l & 15;
        const uint32_t bF = sBu +
            (uint32_t)((wn * 8 + (l2 & 7)) * 264 + ((l2 >> 3) & 1) * 8) * 2;

        float fa[2][4];
        #pragma unroll
        for (int mt = 0; mt < 2; mt++)
            #pragma unroll
            for (int q = 0; q < 4; q++) fa[mt][q] = 0.f;

        #pragma unroll 4
        for (int s = 0; s < 16; s++) {
            const int kg = s * 16;
            uint32_t a0[4], a1[4], bb[2];
            ldsm4(a0, cA0 + kg * 2);
            ldsm4(a1, cA1 + kg * 2);
            ldsm2(bb, bF + kg * 2);
            mma_f16(fa[0], a0, bb[0], bb[1]);
            mma_f16(fa[1], a1, bb[0], bb[1]);
        }

        #pragma unroll
        for (int mt = 0; mt < 2; mt++) {
            const int row = m0 + wm * 32 + mt * 16 + g;
            const int col = wn * 8 + tig * 2;
            #pragma unroll
            for (int h = 0; h < 2; h++) {
                const int rr = row + h * 8;
                if (rr < NP) {
                    if (col < 27)
                        out[(size_t)rr * 27 + col]     = fa[mt][h * 2 + 0] + fcf_b[col];
                    if (col + 1 < 27)
                        out[(size_t)rr * 27 + col + 1] = fa[mt][h * 2 + 1] + fcf_b[col + 1];
                }
            }
        }
    }
}

// ---------------------------------------------------------------------------
extern "C" void kernel_launch(void* const* d_in, const int* in_sizes, int n_in,
                              void* d_out, int out_size)
{
    const float* images  = (const float*)d_in[0];
    const float* conv1_w = (const float*)d_in[1];
    const float* conv1_b = (const float*)d_in[2];
    const float* conv2_w = (const float*)d_in[3];
    const float* conv2_b = (const float*)d_in[4];
    const float* fc1_w   = (const float*)d_in[5];
    const float* fc1_b   = (const float*)d_in[6];
    const float* fc2_w   = (const float*)d_in[7];
    const float* fc2_b   = (const float*)d_in[8];
    const float* fc3_w   = (const float*)d_in[9];
    const float* fc3_b   = (const float*)d_in[10];
    const float* fcf_w   = (const float*)d_in[11];
    const float* fcf_b   = (const float*)d_in[12];
    float* out = (float*)d_out;

    cudaFuncSetAttribute(conv_mma_kernel,
                         cudaFuncAttributeMaxDynamicSharedMemorySize, CV_SMEM);
    conv_mma_kernel<<<NP / 8, 512, CV_SMEM>>>(images, conv1_w, conv1_b,
                                              conv2_w, conv2_b);

    cudaFuncSetAttribute(mlp_mma_kernel,
                         cudaFuncAttributeMaxDynamicSharedMemorySize, ML_SMEM);
    mlp_mma_kernel<<<MROWS_PAD / 128, 512, ML_SMEM>>>(
        fc1_w, fc1_b, fc2_w, fc2_b, fc3_w, fc3_b, fcf_w, fcf_b, out);
}

// round 8
// speedup vs baseline: 6.1903x; 1.5785x over previous
#include <cuda_runtime.h>
#include <cuda_fp16.h>
#include <cstdint>

#define NP 76832          // 32 * 49 * 49 patches
#define HN 49
#define SLEN 104
#define MROWS_PAD 76928   // 601 * 128

// conv output scratch, fp16 (zero-init; pad rows stay zero)
__device__ __half g_h2[(size_t)MROWS_PAD * 1280];
// pre-converted fp16 weights
__device__ __align__(16) __half g_fc1h[256 * 1280];
__device__ __align__(16) __half g_fc2h[256 * 256];
__device__ __align__(16) __half g_fc3h[256 * 256];
__device__ __align__(16) __half g_fcfh[32 * 264];     // zero-padded
__device__ __align__(16) __half g_w2h[9 * 24 * 40];   // [tap][oc][ic] zero-padded

// ---------------------------------------------------------------------------
__device__ __forceinline__ uint32_t s2u(const void* p) {
    return (uint32_t)__cvta_generic_to_shared(p);
}
__device__ __forceinline__ void ldsm4(uint32_t* r, uint32_t addr) {
    asm volatile("ldmatrix.sync.aligned.m8n8.x4.shared.b16 {%0,%1,%2,%3}, [%4];"
        : "=r"(r[0]), "=r"(r[1]), "=r"(r[2]), "=r"(r[3]) : "r"(addr));
}
__device__ __forceinline__ void ldsm2(uint32_t* r, uint32_t addr) {
    asm volatile("ldmatrix.sync.aligned.m8n8.x2.shared.b16 {%0,%1}, [%2];"
        : "=r"(r[0]), "=r"(r[1]) : "r"(addr));
}
__device__ __forceinline__ void mma_f16(float* c, const uint32_t* a,
                                        uint32_t b0, uint32_t b1) {
    asm volatile(
        "mma.sync.aligned.m16n8k16.row.col.f32.f16.f16.f32 "
        "{%0,%1,%2,%3}, {%4,%5,%6,%7}, {%8,%9}, {%0,%1,%2,%3};"
        : "+f"(c[0]), "+f"(c[1]), "+f"(c[2]), "+f"(c[3])
        : "r"(a[0]), "r"(a[1]), "r"(a[2]), "r"(a[3]), "r"(b0), "r"(b1));
}
__device__ __forceinline__ uint32_t pack_h2(float a, float b) {
    __half2 h = __floats2half2_rn(a, b);
    return *(uint32_t*)&h;
}
__device__ __forceinline__ void cp16(uint32_t dst, const void* src) {
    asm volatile("cp.async.ca.shared.global [%0], [%1], 16;"
        :: "r"(dst), "l"(src));
}
#define CP_COMMIT() asm volatile("cp.async.commit_group;" ::: "memory")
#define CP_WAIT0()  asm volatile("cp.async.wait_group 0;" ::: "memory")
#define CP_WAIT1()  asm volatile("cp.async.wait_group 1;" ::: "memory")

// ===========================================================================
// Kernel 0: one-shot fp16 weight conversion / re-layout
// ===========================================================================
__global__ __launch_bounds__(256) void convert_kernel(
    const float* __restrict__ fc1_w, const float* __restrict__ fc2_w,
    const float* __restrict__ fc3_w, const float* __restrict__ fcf_w,
    const float* __restrict__ w2)
{
    const int i = blockIdx.x * 256 + threadIdx.x;
    if (i < 256 * 1280) g_fc1h[i] = __float2half(fc1_w[i]);
    if (i < 256 * 256) {
        g_fc2h[i] = __float2half(fc2_w[i]);
        g_fc3h[i] = __float2half(fc3_w[i]);
    }
    if (i < 32 * 264) {
        int r = i / 264, k = i % 264;
        g_fcfh[i] = (r < 27 && k < 256) ? __float2half(fcf_w[r * 256 + k])
                                        : __half(0.f);
    }
    if (i < 9 * 24 * 40) {
        int tap = i / 960, r = i % 960, oc = r / 40, ic = r % 40;
        g_w2h[i] = (oc < 20 && ic < 20)
                 ? __float2half(w2[oc * 180 + ic * 9 + tap]) : __half(0.f);
    }
}

// ===========================================================================
// Kernel 1: conv1 (FFMA f32) + conv2 (fp16 mma via ldmatrix)
// 4 patches / CTA, 256 threads = 8 warps (2 warps per patch). ~52KB smem.
// ===========================================================================
#define CV_H1   0          // 4 lp x 100 rows x 40 halves = 32000 B
#define CV_W2   32000      // 9 x 24 x 40 halves          = 17280 B
#define CV_IN   49280      // 4 x 2 x 100 f32             = 3200 B
#define CV_W1   52480      // 480 f32                     = 1920 B
#define CV_B1   54400      // 20 f32
#define CV_B2   54480      // 24 f32
#define CV_SMEM 54576

__global__ __launch_bounds__(256) void conv_mma_kernel(
    const float* __restrict__ images,
    const float* __restrict__ w1, const float* __restrict__ b1,
    const float* __restrict__ b2)
{
    extern __shared__ __align__(16) char smc[];
    __half* sH1 = (__half*)(smc + CV_H1);
    __half* sW2 = (__half*)(smc + CV_W2);
    float*  sIn = (float*)(smc + CV_IN);
    float*  sW1 = (float*)(smc + CV_W1);
    float*  sB1 = (float*)(smc + CV_B1);
    float*  sB2 = (float*)(smc + CV_B2);

    const int tid = threadIdx.x;

    // zero-fill sH1 pads + sIn pads
    {
        uint32_t* z = (uint32_t*)smc;
        for (int i = tid; i < 32000 / 4; i += 256) z[i] = 0u;
        for (int i = tid; i < 800; i += 256) sIn[i] = 0.f;
    }
    // copy pre-packed conv2 weights (1080 uint4)
    for (int i = tid; i < 1080; i += 256)
        ((uint4*)sW2)[i] = ((const uint4*)g_w2h)[i];
    // conv1 weights
    for (int i = tid; i < 20 * 2 * 9; i += 256) {
        int oc = i / 18, r = i % 18, ic = r / 9, t = r % 9;
        sW1[(oc * 2 + ic) * 12 + t] = w1[i];
    }
    if (tid < 20) sB1[tid] = b1[tid];
    if (tid < 24) sB2[tid] = (tid < 20) ? b2[tid] : 0.f;

    // load input patches
    const int lp  = tid >> 6;          // 0..3
    const int pix = tid & 63;
    const int y = pix >> 3, x = pix & 7;
    const int patch = blockIdx.x * 4 + lp;
    const int b  = patch / (HN * HN);
    const int t2 = patch % (HN * HN);
    const int i0 = (t2 / HN) * 2, j0 = (t2 % HN) * 2;
    __syncthreads();
    #pragma unroll
    for (int c = 0; c < 2; c++) {
        sIn[(lp * 2 + c) * 100 + (y + 1) * 10 + (x + 1)] =
            images[((size_t)(b * 2 + c) * SLEN + (i0 + y)) * SLEN + (j0 + x)];
    }
    __syncthreads();

    // ---- conv1: one pixel per thread ----
    {
        float v[2][9];
        #pragma unroll
        for (int c = 0; c < 2; c++)
            #pragma unroll
            for (int dy = 0; dy < 3; dy++)
                #pragma unroll
                for (int dx = 0; dx < 3; dx++)
                    v[c][dy * 3 + dx] = sIn[(lp * 2 + c) * 100 + (y + dy) * 10 + (x + dx)];
        const int rr = (y + 1) * 10 + (x + 1);
        #pragma unroll
        for (int ocp = 0; ocp < 10; ocp++) {
            float acc0 = sB1[2 * ocp], acc1 = sB1[2 * ocp + 1];
            #pragma unroll
            for (int c = 0; c < 2; c++) {
                const float* wa = &sW1[((2 * ocp) * 2 + c) * 12];
                const float* wb = &sW1[((2 * ocp + 1) * 2 + c) * 12];
                #pragma unroll
                for (int t = 0; t < 9; t++) {
                    acc0 += v[c][t] * wa[t];
                    acc1 += v[c][t] * wb[t];
                }
            }
            *(uint32_t*)&sH1[lp * 4000 + rr * 40 + 2 * ocp] =
                pack_h2(fmaxf(acc0, 0.f), fmaxf(acc1, 0.f));
        }
    }
    __syncthreads();

    // ---- conv2 via fp16 mma + ldmatrix ----
    const int l    = tid & 31;
    const int wid  = tid >> 5;
    const int lp_w = wid >> 1;
    const int hf   = wid & 1;
    const int g    = l >> 2;
    const int tig  = l & 3;

    const uint32_t sH1u = s2u(sH1 + lp_w * 4000);
    const uint32_t sW2u = s2u(sW2);

    const int l16 = l & 15, lg = l >> 4;
    const int pA0 = hf * 32 + l16;
    const int pA1 = pA0 + 16;
    const int rA0 = (pA0 >> 3) * 10 + (pA0 & 7);
    const int rA1 = (pA1 >> 3) * 10 + (pA1 & 7);
    const uint32_t aB0 = sH1u + (uint32_t)(rA0 * 40 + lg * 8) * 2;
    const uint32_t aB1 = sH1u + (uint32_t)(rA1 * 40 + lg * 8) * 2;

    const int bt   = l >> 3;
    const int bn01 = (bt >> 1) * 8 + (l & 7);
    const int bk01 = (bt & 1) * 8;
    const uint32_t bB01 = sW2u + (uint32_t)(bn01 * 40 + bk01) * 2;
    const int l2  = l & 15;
    const int bn2 = 16 + (l2 & 7);
    const int bk2 = ((l2 >> 3) & 1) * 8;
    const uint32_t bB2 = sW2u + (uint32_t)(bn2 * 40 + bk2) * 2;

    float acc[2][3][4];
    #pragma unroll
    for (int mt = 0; mt < 2; mt++)
        #pragma unroll
        for (int nt = 0; nt < 3; nt++)
            #pragma unroll
            for (int q = 0; q < 4; q++) acc[mt][nt][q] = 0.f;

    #pragma unroll
    for (int tap = 0; tap < 9; tap++) {
        const int dy = tap / 3, dx = tap % 3;
        const uint32_t ro = (uint32_t)((dy * 10 + dx) * 40) * 2;
        const uint32_t wo = (uint32_t)(tap * 960) * 2;
        #pragma unroll
        for (int c = 0; c < 2; c++) {
            const uint32_t ko = (uint32_t)(c * 16) * 2;
            uint32_t a0[4], a1[4], b01[4], bb2[2];
            ldsm4(a0, aB0 + ro + ko);
            ldsm4(a1, aB1 + ro + ko);
            ldsm4(b01, bB01 + wo + ko);
            ldsm2(bb2, bB2 + wo + ko);
            mma_f16(acc[0][0], a0, b01[0], b01[1]);
            mma_f16(acc[0][1], a0, b01[2], b01[3]);
            mma_f16(acc[0][2], a0, bb2[0], bb2[1]);
            mma_f16(acc[1][0], a1, b01[0], b01[1]);
            mma_f16(acc[1][1], a1, b01[2], b01[3]);
            mma_f16(acc[1][2], a1, bb2[0], bb2[1]);
        }
    }
    __syncthreads();

    // ---- epilogue: bias+relu -> f32 staging over sH1 region ----
    float* stg = (float*)smc;                 // 4*1300*4 = 20800 B <= 32000
    float* stw = stg + lp_w * 1300;
    #pragma unroll
    for (int mt = 0; mt < 2; mt++) {
        const int row = hf * 32 + mt * 16 + g;
        #pragma unroll
        for (int nt = 0; nt < 3; nt++) {
            const int col = nt * 8 + tig * 2;
            if (col < 20) {
                stw[col * 65 + row]     = fmaxf(acc[mt][nt][0] + sB2[col], 0.f);
                stw[col * 65 + row + 8] = fmaxf(acc[mt][nt][2] + sB2[col], 0.f);
            }
            if (col + 1 < 20) {
                stw[(col + 1) * 65 + row]     = fmaxf(acc[mt][nt][1] + sB2[col + 1], 0.f);
                stw[(col + 1) * 65 + row + 8] = fmaxf(acc[mt][nt][3] + sB2[col + 1], 0.f);
            }
        }
    }
    __syncthreads();

    // ---- coalesced fp16 write to g_h2 ----
    for (int i = tid; i < 4 * 20 * 32; i += 256) {
        const int lp2 = i / 640, r = i % 640, oc = r >> 5, pp = r & 31;
        const float* s = stg + lp2 * 1300 + oc * 65;
        const int patch2 = blockIdx.x * 4 + lp2;
        ((uint32_t*)(g_h2 + (size_t)patch2 * 1280 + oc * 64))[pp] =
            pack_h2(s[2 * pp], s[2 * pp + 1]);
    }
}

// ===========================================================================
// Kernel 2: fused MLP, fp16 mma + ldmatrix + cp.async pipeline (3 bufs, depth 2)
// ===========================================================================
// smem byte offsets
#define ML_ACT  0                       // 128 x 264 halves = 67584
#define ML_B    67584                   // 3 x (256 x 40 halves) = 3 x 20480
#define ML_A    (67584 + 61440)         // 3 x (128 x 40 halves) = 3 x 10240
#define ML_SMEM (67584 + 61440 + 30720) // 159744

__global__ __launch_bounds__(512, 1) void mlp_mma_kernel(
    const float* __restrict__ fc1_b, const float* __restrict__ fc2_b,
    const float* __restrict__ fc3_b, const float* __restrict__ fcf_b,
    float* __restrict__ out)
{
    extern __shared__ __align__(16) char smc[];
    __half* sAct = (__half*)(smc + ML_ACT);

    const int tid  = threadIdx.x;
    const int l    = tid & 31;
    const int wid  = tid >> 5;
    const int wm   = wid >> 2;
    const int wn   = wid & 3;
    const int g    = l >> 2;
    const int tig  = l & 3;
    const int m0   = blockIdx.x * 128;

    const uint32_t sActu = s2u(smc + ML_ACT);
    const uint32_t sBu   = s2u(smc + ML_B);
    const uint32_t sAu   = s2u(smc + ML_A);

    // ldmatrix lane geometry (byte offsets relative to buffer base)
    const int l16 = l & 15, lg = l >> 4;
    const uint32_t relA0 = (uint32_t)((wm * 32 + l16) * 40 + lg * 8) * 2;
    const uint32_t relA1 = relA0 + 16 * 40 * 2;
    const uint32_t cA0 = sActu + (uint32_t)((wm * 32 + l16) * 264 + lg * 8) * 2;
    const uint32_t cA1 = cA0 + 16 * 264 * 2;
    const int bt = l >> 3;
    const int bnl = (bt >> 1) * 8 + (l & 7);
    const int bkl = (bt & 1) * 8;
    uint32_t relB[4];
    #pragma unroll
    for (int gn = 0; gn < 4; gn++)
        relB[gn] = (uint32_t)((wn * 64 + gn * 16 + bnl) * 40 + bkl) * 2;

    // cp.async staging mapping
    const int rB = tid >> 2, qB = tid & 3;     // B: two passes of 128 rows
    const int rA = tid >> 2, qA = tid & 3;     // A: 128 rows x 4 quads

    float acc[2][8][4];

    // ================= fc1: K=1280, 40 chunks, A from g_h2 =================
    {
        #pragma unroll
        for (int mt = 0; mt < 2; mt++)
            #pragma unroll
            for (int nt = 0; nt < 8; nt++)
                #pragma unroll
                for (int q = 0; q < 4; q++) acc[mt][nt][q] = 0.f;

        // issue chunk into buffer (fc1)
        auto issue1 = [&](int c) {
            const uint32_t bb = sBu + (uint32_t)(c % 3) * 20480;
            const uint32_t ab = sAu + (uint32_t)(c % 3) * 10240;
            const __half* bsrc = g_fc1h + (size_t)rB * 1280 + c * 32 + qB * 8;
            cp16(bb + (uint32_t)(rB * 40 + qB * 8) * 2, bsrc);
            cp16(bb + (uint32_t)((rB + 128) * 40 + qB * 8) * 2, bsrc + 128 * 1280);
            cp16(ab + (uint32_t)(rA * 40 + qA * 8) * 2,
                 g_h2 + (size_t)(m0 + rA) * 1280 + c * 32 + qA * 8);
            CP_COMMIT();
        };
        issue1(0); issue1(1);

        for (int c = 0; c < 40; c++) {
            if (c + 2 < 40) { CP_WAIT1(); } else { CP_WAIT0(); }
            __syncthreads();
            if (c + 2 < 40) issue1(c + 2);
            const uint32_t bb = sBu + (uint32_t)(c % 3) * 20480;
            const uint32_t ab = sAu + (uint32_t)(c % 3) * 10240;
            #pragma unroll
            for (int kk = 0; kk < 32; kk += 16) {
                uint32_t a0[4], a1[4];
                ldsm4(a0, ab + relA0 + kk * 2);
                ldsm4(a1, ab + relA1 + kk * 2);
                #pragma unroll
                for (int gn = 0; gn < 4; gn++) {
                    uint32_t bbv[4];
                    ldsm4(bbv, bb + relB[gn] + kk * 2);
                    mma_f16(acc[0][2 * gn],     a0, bbv[0], bbv[1]);
                    mma_f16(acc[0][2 * gn + 1], a0, bbv[2], bbv[3]);
                    mma_f16(acc[1][2 * gn],     a1, bbv[0], bbv[1]);
                    mma_f16(acc[1][2 * gn + 1], a1, bbv[2], bbv[3]);
                }
            }
        }
        __syncthreads();
        #pragma unroll
        for (int mt = 0; mt < 2; mt++)
            #pragma unroll
            for (int nt = 0; nt < 8; nt++) {
                const int row = wm * 32 + mt * 16 + g;
                const int col = wn * 64 + nt * 8 + tig * 2;
                const float b0 = fc1_b[col], b1 = fc1_b[col + 1];
                *(uint32_t*)&sAct[row * 264 + col] =
                    pack_h2(fmaxf(acc[mt][nt][0] + b0, 0.f),
                            fmaxf(acc[mt][nt][1] + b1, 0.f));
                *(uint32_t*)&sAct[(row + 8) * 264 + col] =
                    pack_h2(fmaxf(acc[mt][nt][2] + b0, 0.f),
                            fmaxf(acc[mt][nt][3] + b1, 0.f));
            }
        __syncthreads();
    }

    // ================= fc2 & fc3: K=256, 8 chunks =================
    for (int layer = 0; layer < 2; layer++) {
        const __half* wg = layer ? g_fc3h : g_fc2h;
        const float*  bg = layer ? fc3_b : fc2_b;
        #pragma unroll
        for (int mt = 0; mt < 2; mt++)
            #pragma unroll
            for (int nt = 0; nt < 8; nt++)
                #pragma unroll
                for (int q = 0; q < 4; q++) acc[mt][nt][q] = 0.f;

        auto issue2 = [&](int c) {
            const uint32_t bb = sBu + (uint32_t)(c % 3) * 20480;
            const __half* bsrc = wg + (size_t)rB * 256 + c * 32 + qB * 8;
            cp16(bb + (uint32_t)(rB * 40 + qB * 8) * 2, bsrc);
            cp16(bb + (uint32_t)((rB + 128) * 40 + qB * 8) * 2, bsrc + 128 * 256);
            CP_COMMIT();
        };
        issue2(0); issue2(1);

        for (int c = 0; c < 8; c++) {
            if (c + 2 < 8) { CP_WAIT1(); } else { CP_WAIT0(); }
            __syncthreads();
            if (c + 2 < 8) issue2(c + 2);
            const uint32_t bb = sBu + (uint32_t)(c % 3) * 20480;
            #pragma unroll
            for (int kk = 0; kk < 32; kk += 16) {
                const int kg = c * 32 + kk;
                uint32_t a0[4], a1[4];
                ldsm4(a0, cA0 + kg * 2);
                ldsm4(a1, cA1 + kg * 2);
                #pragma unroll
                for (int gn = 0; gn < 4; gn++) {
                    uint32_t bbv[4];
                    ldsm4(bbv, bb + relB[gn] + kk * 2);
                    mma_f16(acc[0][2 * gn],     a0, bbv[0], bbv[1]);
                    mma_f16(acc[0][2 * gn + 1], a0, bbv[2], bbv[3]);
                    mma_f16(acc[1][2 * gn],     a1, bbv[0], bbv[1]);
                    mma_f16(acc[1][2 * gn + 1], a1, bbv[2], bbv[3]);
                }
            }
        }
        __syncthreads();
        #pragma unroll
        for (int mt = 0; mt < 2; mt++)
            #pragma unroll
            for (int nt = 0; nt < 8; nt++) {
                const int row = wm * 32 + mt * 16 + g;
                const int col = wn * 64 + nt * 8 + tig * 2;
                const float b0 = bg[col], b1 = bg[col + 1];
                *(uint32_t*)&sAct[row * 264 + col] =
                    pack_h2(fmaxf(acc[mt][nt][0] + b0, 0.f),
                            fmaxf(acc[mt][nt][1] + b1, 0.f));
                *(uint32_t*)&sAct[(row + 8) * 264 + col] =
                    pack_h2(fmaxf(acc[mt][nt][2] + b0, 0.f),
                            fmaxf(acc[mt][nt][3] + b1, 0.f));
            }
        __syncthreads();
    }

    // ================= fcf: K=256, N=27 (pad 32) =================
    {
        // copy pre-padded fcf weights [32][264] into B buffer 0
        __half* sB0 = (__half*)(smc + ML_B);
        for (int i = tid; i < 1056; i += 512)
            ((uint4*)sB0)[i] = ((const uint4*)g_fcfh)[i];
        __syncthreads();

        const int l2b = l & 15;
        const uint32_t bF = sBu +
            (uint32_t)((wn * 8 + (l2b & 7)) * 264 + ((l2b >> 3) & 1) * 8) * 2;

        float fa[2][4];
        #pragma unroll
        for (int mt = 0; mt < 2; mt++)
            #pragma unroll
            for (int q = 0; q < 4; q++) fa[mt][q] = 0.f;

        #pragma unroll 4
        for (int s = 0; s < 16; s++) {
            const int kg = s * 16;
            uint32_t a0[4], a1[4], bb[2];
            ldsm4(a0, cA0 + kg * 2);
            ldsm4(a1, cA1 + kg * 2);
            ldsm2(bb, bF + kg * 2);
            mma_f16(fa[0], a0, bb[0], bb[1]);
            mma_f16(fa[1], a1, bb[0], bb[1]);
        }

        #pragma unroll
        for (int mt = 0; mt < 2; mt++) {
            const int row = m0 + wm * 32 + mt * 16 + g;
            const int col = wn * 8 + tig * 2;
            #pragma unroll
            for (int h = 0; h < 2; h++) {
                const int rr = row + h * 8;
                if (rr < NP) {
                    if (col < 27)
                        out[(size_t)rr * 27 + col]     = fa[mt][h * 2 + 0] + fcf_b[col];
                    if (col + 1 < 27)
                        out[(size_t)rr * 27 + col + 1] = fa[mt][h * 2 + 1] + fcf_b[col + 1];
                }
            }
        }
    }
}

// ---------------------------------------------------------------------------
extern "C" void kernel_launch(void* const* d_in, const int* in_sizes, int n_in,
                              void* d_out, int out_size)
{
    const float* images  = (const float*)d_in[0];
    const float* conv1_w = (const float*)d_in[1];
    const float* conv1_b = (const float*)d_in[2];
    const float* conv2_w = (const float*)d_in[3];
    const float* conv2_b = (const float*)d_in[4];
    const float* fc1_w   = (const float*)d_in[5];
    const float* fc1_b   = (const float*)d_in[6];
    const float* fc2_w   = (const float*)d_in[7];
    const float* fc2_b   = (const float*)d_in[8];
    const float* fc3_w   = (const float*)d_in[9];
    const float* fc3_b   = (const float*)d_in[10];
    const float* fcf_w   = (const float*)d_in[11];
    const float* fcf_b   = (const float*)d_in[12];
    float* out = (float*)d_out;

    convert_kernel<<<1280, 256>>>(fc1_w, fc2_w, fc3_w, fcf_w, conv2_w);

    cudaFuncSetAttribute(conv_mma_kernel,
                         cudaFuncAttributeMaxDynamicSharedMemorySize, CV_SMEM);
    conv_mma_kernel<<<NP / 4, 256, CV_SMEM>>>(images, conv1_w, conv1_b, conv2_b);

    cudaFuncSetAttribute(mlp_mma_kernel,
                         cudaFuncAttributeMaxDynamicSharedMemorySize, ML_SMEM);
    mlp_mma_kernel<<<MROWS_PAD / 128, 512, ML_SMEM>>>(
        fc1_b, fc2_b, fc3_b, fcf_b, out);
}

// round 9
// speedup vs baseline: 6.6323x; 1.0714x over previous
#include <cuda_runtime.h>
#include <cuda_fp16.h>
#include <cstdint>

#define NP 76832          // 32 * 49 * 49 patches
#define HN 49
#define SLEN 104
#define MROWS_PAD 76928   // 601 * 128

// conv output scratch, fp16, layout [patch][pix*20 + oc] (zero-init; pad rows zero)
__device__ __half g_h2[(size_t)MROWS_PAD * 1280];
// pre-converted fp16 weights
__device__ __align__(16) __half g_fc1h[256 * 1280];   // K permuted to pix*20+oc
__device__ __align__(16) __half g_fc2h[256 * 256];
__device__ __align__(16) __half g_fc3h[256 * 256];
__device__ __align__(16) __half g_fcfh[32 * 264];     // zero-padded
__device__ __align__(16) __half g_w2h[3 * 24 * 80];   // [dy][oc][dx*24+ic], zero-pad

// ---------------------------------------------------------------------------
__device__ __forceinline__ uint32_t s2u(const void* p) {
    return (uint32_t)__cvta_generic_to_shared(p);
}
__device__ __forceinline__ void ldsm4(uint32_t* r, uint32_t addr) {
    asm volatile("ldmatrix.sync.aligned.m8n8.x4.shared.b16 {%0,%1,%2,%3}, [%4];"
        : "=r"(r[0]), "=r"(r[1]), "=r"(r[2]), "=r"(r[3]) : "r"(addr));
}
__device__ __forceinline__ void ldsm2(uint32_t* r, uint32_t addr) {
    asm volatile("ldmatrix.sync.aligned.m8n8.x2.shared.b16 {%0,%1}, [%2];"
        : "=r"(r[0]), "=r"(r[1]) : "r"(addr));
}
__device__ __forceinline__ void mma_f16(float* c, const uint32_t* a,
                                        uint32_t b0, uint32_t b1) {
    asm volatile(
        "mma.sync.aligned.m16n8k16.row.col.f32.f16.f16.f32 "
        "{%0,%1,%2,%3}, {%4,%5,%6,%7}, {%8,%9}, {%0,%1,%2,%3};"
        : "+f"(c[0]), "+f"(c[1]), "+f"(c[2]), "+f"(c[3])
        : "r"(a[0]), "r"(a[1]), "r"(a[2]), "r"(a[3]), "r"(b0), "r"(b1));
}
__device__ __forceinline__ uint32_t pack_h2(float a, float b) {
    __half2 h = __floats2half2_rn(a, b);
    return *(uint32_t*)&h;
}
__device__ __forceinline__ void cp16(uint32_t dst, const void* src) {
    asm volatile("cp.async.ca.shared.global [%0], [%1], 16;"
        :: "r"(dst), "l"(src));
}
#define CP_COMMIT() asm volatile("cp.async.commit_group;" ::: "memory")
#define CP_WAIT0()  asm volatile("cp.async.wait_group 0;" ::: "memory")
#define CP_WAIT1()  asm volatile("cp.async.wait_group 1;" ::: "memory")

// ===========================================================================
// Kernel 0: one-shot fp16 weight conversion / re-layout
// ===========================================================================
__global__ __launch_bounds__(256) void convert_kernel(
    const float* __restrict__ fc1_w, const float* __restrict__ fc2_w,
    const float* __restrict__ fc3_w, const float* __restrict__ fcf_w,
    const float* __restrict__ w2)
{
    const int i = blockIdx.x * 256 + threadIdx.x;
    if (i < 256 * 1280) {
        // permute K: original k = oc*64 + pix  ->  new k' = pix*20 + oc
        int n = i / 1280, k = i % 1280;
        int oc = k / 64, pix = k % 64;
        g_fc1h[(size_t)n * 1280 + pix * 20 + oc] = __float2half(fc1_w[i]);
    }
    if (i < 256 * 256) {
        g_fc2h[i] = __float2half(fc2_w[i]);
        g_fc3h[i] = __float2half(fc3_w[i]);
    }
    if (i < 32 * 264) {
        int r = i / 264, k = i % 264;
        g_fcfh[i] = (r < 27 && k < 256) ? __float2half(fcf_w[r * 256 + k])
                                        : __half(0.f);
    }
    if (i < 3 * 24 * 80) {
        int dy = i / 1920, r = i % 1920, oc = r / 80, k = r % 80;
        int dx = k / 24, ic = k % 24;
        g_w2h[i] = (oc < 20 && k < 72 && ic < 20)
                 ? __float2half(w2[oc * 180 + ic * 9 + dy * 3 + dx]) : __half(0.f);
    }
}

// ===========================================================================
// Kernel 1: conv1 (FFMA f32) + conv2 (fp16 mma, dx-packed K)
// 4 patches / CTA, 256 threads = 8 warps (2 warps per patch). ~36KB smem.
// sH1: per patch 100 padded pixels x 24 halves (stride 24, ic 20 valid)
// ===========================================================================
#define CV_H1   0          // 4*2400 + 16 pad = 9616 halves = 19232 B
#define CV_W2   19232      // 3*24*80 halves  = 11520 B
#define CV_IN   30752      // 800 f32 = 3200 B
#define CV_W1   33952      // 480 f32 = 1920 B
#define CV_B1   35872      // 20 f32
#define CV_B2   35952      // 24 f32
#define CV_SMEM 36048

__global__ __launch_bounds__(256) void conv_mma_kernel(
    const float* __restrict__ images,
    const float* __restrict__ w1, const float* __restrict__ b1,
    const float* __restrict__ b2)
{
    extern __shared__ __align__(16) char smc[];
    __half* sH1 = (__half*)(smc + CV_H1);
    __half* sW2 = (__half*)(smc + CV_W2);
    float*  sIn = (float*)(smc + CV_IN);
    float*  sW1 = (float*)(smc + CV_W1);
    float*  sB1 = (float*)(smc + CV_B1);
    float*  sB2 = (float*)(smc + CV_B2);

    const int tid = threadIdx.x;

    // zero-fill sH1 (all of it: mma reads pads with zero weights; must be finite)
    {
        uint32_t* z = (uint32_t*)smc;
        for (int i = tid; i < 19232 / 4; i += 256) z[i] = 0u;
        for (int i = tid; i < 800; i += 256) sIn[i] = 0.f;
    }
    // copy pre-packed conv2 weights (720 uint4)
    for (int i = tid; i < 720; i += 256)
        ((uint4*)sW2)[i] = ((const uint4*)g_w2h)[i];
    // conv1 weights
    for (int i = tid; i < 20 * 2 * 9; i += 256) {
        int oc = i / 18, r = i % 18, ic = r / 9, t = r % 9;
        sW1[(oc * 2 + ic) * 12 + t] = w1[i];
    }
    if (tid < 20) sB1[tid] = b1[tid];
    if (tid < 24) sB2[tid] = (tid < 20) ? b2[tid] : 0.f;

    // load input patches
    const int lp  = tid >> 6;          // 0..3
    const int pix = tid & 63;
    const int y = pix >> 3, x = pix & 7;
    const int patch = blockIdx.x * 4 + lp;
    const int b  = patch / (HN * HN);
    const int t2 = patch % (HN * HN);
    const int i0 = (t2 / HN) * 2, j0 = (t2 % HN) * 2;
    __syncthreads();
    #pragma unroll
    for (int c = 0; c < 2; c++) {
        sIn[(lp * 2 + c) * 100 + (y + 1) * 10 + (x + 1)] =
            images[((size_t)(b * 2 + c) * SLEN + (i0 + y)) * SLEN + (j0 + x)];
    }
    __syncthreads();

    // ---- conv1: one pixel per thread, write [padded pixel][ic] stride 24 ----
    {
        float v[2][9];
        #pragma unroll
        for (int c = 0; c < 2; c++)
            #pragma unroll
            for (int dy = 0; dy < 3; dy++)
                #pragma unroll
                for (int dx = 0; dx < 3; dx++)
                    v[c][dy * 3 + dx] = sIn[(lp * 2 + c) * 100 + (y + dy) * 10 + (x + dx)];
        const int rr = (y + 1) * 10 + (x + 1);
        #pragma unroll
        for (int ocp = 0; ocp < 10; ocp++) {
            float acc0 = sB1[2 * ocp], acc1 = sB1[2 * ocp + 1];
            #pragma unroll
            for (int c = 0; c < 2; c++) {
                const float* wa = &sW1[((2 * ocp) * 2 + c) * 12];
                const float* wb = &sW1[((2 * ocp + 1) * 2 + c) * 12];
                #pragma unroll
                for (int t = 0; t < 9; t++) {
                    acc0 += v[c][t] * wa[t];
                    acc1 += v[c][t] * wb[t];
                }
            }
            *(uint32_t*)&sH1[lp * 2400 + rr * 24 + 2 * ocp] =
                pack_h2(fmaxf(acc0, 0.f), fmaxf(acc1, 0.f));
        }
    }
    __syncthreads();

    // ---- conv2 via fp16 mma, K = dx*24+ic per dy (3 dy x 5 k16-chunks) ----
    const int l    = tid & 31;
    const int wid  = tid >> 5;
    const int lp_w = wid >> 1;
    const int hf   = wid & 1;
    const int g    = l >> 2;
    const int tig  = l & 3;

    const uint32_t sH1u = s2u(sH1 + lp_w * 2400);
    const uint32_t sW2u = s2u(sW2);

    const int l16 = l & 15, lg = l >> 4;
    const int pA0 = hf * 32 + l16;            // pixel for m16 tile row
    const int pA1 = pA0 + 16;
    // A row base (dy = 0): padded row (y0)*10 + x0, stride 24 halves (48 B)
    const uint32_t aB0 = sH1u +
        (uint32_t)((((pA0 >> 3)) * 10 + (pA0 & 7)) * 24 + lg * 8) * 2;
    const uint32_t aB1 = sH1u +
        (uint32_t)((((pA1 >> 3)) * 10 + (pA1 & 7)) * 24 + lg * 8) * 2;

    // B frag addressing: rows = oc (stride 80 halves)
    const int bt   = l >> 3;
    const int bn01 = (bt >> 1) * 8 + (l & 7);
    const int bk01 = (bt & 1) * 8;
    const uint32_t bB01 = sW2u + (uint32_t)(bn01 * 80 + bk01) * 2;
    const int l2  = l & 15;
    const int bn2 = 16 + (l2 & 7);
    const int bk2 = ((l2 >> 3) & 1) * 8;
    const uint32_t bB2 = sW2u + (uint32_t)(bn2 * 80 + bk2) * 2;

    float acc[2][3][4];
    #pragma unroll
    for (int mt = 0; mt < 2; mt++)
        #pragma unroll
        for (int nt = 0; nt < 3; nt++)
            #pragma unroll
            for (int q = 0; q < 4; q++) acc[mt][nt][q] = 0.f;

    #pragma unroll
    for (int dy = 0; dy < 3; dy++) {
        const uint32_t ro = (uint32_t)dy * 480;    // +10 rows * 48 B
        const uint32_t wo = (uint32_t)dy * 3840;   // +24*80 halves * 2
        #pragma unroll
        for (int c = 0; c < 5; c++) {
            const uint32_t ko = (uint32_t)c * 32;
            uint32_t a0[4], a1[4], b01[4], bb2[2];
            ldsm4(a0, aB0 + ro + ko);
            ldsm4(a1, aB1 + ro + ko);
            ldsm4(b01, bB01 + wo + ko);
            ldsm2(bb2, bB2 + wo + ko);
            mma_f16(acc[0][0], a0, b01[0], b01[1]);
            mma_f16(acc[0][1], a0, b01[2], b01[3]);
            mma_f16(acc[0][2], a0, bb2[0], bb2[1]);
            mma_f16(acc[1][0], a1, b01[0], b01[1]);
            mma_f16(acc[1][1], a1, b01[2], b01[3]);
            mma_f16(acc[1][2], a1, bb2[0], bb2[1]);
        }
    }

    // ---- direct epilogue: bias+relu -> g_h2[patch][pix*20 + oc] ----
    {
        __half* dst = g_h2 + (size_t)(blockIdx.x * 4 + lp_w) * 1280;
        #pragma unroll
        for (int mt = 0; mt < 2; mt++) {
            const int row = hf * 32 + mt * 16 + g;
            #pragma unroll
            for (int nt = 0; nt < 3; nt++) {
                const int col = nt * 8 + tig * 2;
                if (col < 20) {
                    const float b0 = sB2[col], b1v = sB2[col + 1];
                    *(uint32_t*)&dst[row * 20 + col] =
                        pack_h2(fmaxf(acc[mt][nt][0] + b0, 0.f),
                                fmaxf(acc[mt][nt][1] + b1v, 0.f));
                    *(uint32_t*)&dst[(row + 8) * 20 + col] =
                        pack_h2(fmaxf(acc[mt][nt][2] + b0, 0.f),
                                fmaxf(acc[mt][nt][3] + b1v, 0.f));
                }
            }
        }
    }
}

// ===========================================================================
// Kernel 2: fused MLP, fp16 mma + ldmatrix + cp.async pipeline (3 bufs, depth 2)
// ===========================================================================
#define ML_ACT  0                       // 128 x 264 halves = 67584
#define ML_B    67584                   // 3 x (256 x 40 halves) = 3 x 20480
#define ML_A    (67584 + 61440)         // 3 x (128 x 40 halves) = 3 x 10240
#define ML_SMEM (67584 + 61440 + 30720) // 159744

__global__ __launch_bounds__(512, 1) void mlp_mma_kernel(
    const float* __restrict__ fc1_b, const float* __restrict__ fc2_b,
    const float* __restrict__ fc3_b, const float* __restrict__ fcf_b,
    float* __restrict__ out)
{
    extern __shared__ __align__(16) char smc[];
    __half* sAct = (__half*)(smc + ML_ACT);

    const int tid  = threadIdx.x;
    const int l    = tid & 31;
    const int wid  = tid >> 5;
    const int wm   = wid >> 2;
    const int wn   = wid & 3;
    const int g    = l >> 2;
    const int tig  = l & 3;
    const int m0   = blockIdx.x * 128;

    const uint32_t sActu = s2u(smc + ML_ACT);
    const uint32_t sBu   = s2u(smc + ML_B);
    const uint32_t sAu   = s2u(smc + ML_A);

    const int l16 = l & 15, lg = l >> 4;
    const uint32_t relA0 = (uint32_t)((wm * 32 + l16) * 40 + lg * 8) * 2;
    const uint32_t relA1 = relA0 + 16 * 40 * 2;
    const uint32_t cA0 = sActu + (uint32_t)((wm * 32 + l16) * 264 + lg * 8) * 2;
    const uint32_t cA1 = cA0 + 16 * 264 * 2;
    const int bt = l >> 3;
    const int bnl = (bt >> 1) * 8 + (l & 7);
    const int bkl = (bt & 1) * 8;
    uint32_t relB[4];
    #pragma unroll
    for (int gn = 0; gn < 4; gn++)
        relB[gn] = (uint32_t)((wn * 64 + gn * 16 + bnl) * 40 + bkl) * 2;

    const int rB = tid >> 2, qB = tid & 3;
    const int rA = tid >> 2, qA = tid & 3;

    float acc[2][8][4];

    // ================= fc1: K=1280, 40 chunks, A from g_h2 =================
    {
        #pragma unroll
        for (int mt = 0; mt < 2; mt++)
            #pragma unroll
            for (int nt = 0; nt < 8; nt++)
                #pragma unroll
                for (int q = 0; q < 4; q++) acc[mt][nt][q] = 0.f;

        auto issue1 = [&](int c) {
            const uint32_t bb = sBu + (uint32_t)(c % 3) * 20480;
            const uint32_t ab = sAu + (uint32_t)(c % 3) * 10240;
            const __half* bsrc = g_fc1h + (size_t)rB * 1280 + c * 32 + qB * 8;
            cp16(bb + (uint32_t)(rB * 40 + qB * 8) * 2, bsrc);
            cp16(bb + (uint32_t)((rB + 128) * 40 + qB * 8) * 2, bsrc + 128 * 1280);
            cp16(ab + (uint32_t)(rA * 40 + qA * 8) * 2,
                 g_h2 + (size_t)(m0 + rA) * 1280 + c * 32 + qA * 8);
            CP_COMMIT();
        };
        issue1(0); issue1(1);

        for (int c = 0; c < 40; c++) {
            if (c + 2 < 40) { CP_WAIT1(); } else { CP_WAIT0(); }
            __syncthreads();
            if (c + 2 < 40) issue1(c + 2);
            const uint32_t bb = sBu + (uint32_t)(c % 3) * 20480;
            const uint32_t ab = sAu + (uint32_t)(c % 3) * 10240;
            #pragma unroll
            for (int kk = 0; kk < 32; kk += 16) {
                uint32_t a0[4], a1[4];
                ldsm4(a0, ab + relA0 + kk * 2);
                ldsm4(a1, ab + relA1 + kk * 2);
                #pragma unroll
                for (int gn = 0; gn < 4; gn++) {
                    uint32_t bbv[4];
                    ldsm4(bbv, bb + relB[gn] + kk * 2);
                    mma_f16(acc[0][2 * gn],     a0, bbv[0], bbv[1]);
                    mma_f16(acc[0][2 * gn + 1], a0, bbv[2], bbv[3]);
                    mma_f16(acc[1][2 * gn],     a1, bbv[0], bbv[1]);
                    mma_f16(acc[1][2 * gn + 1], a1, bbv[2], bbv[3]);
                }
            }
        }
        __syncthreads();
        #pragma unroll
        for (int mt = 0; mt < 2; mt++)
            #pragma unroll
            for (int nt = 0; nt < 8; nt++) {
                const int row = wm * 32 + mt * 16 + g;
                const int col = wn * 64 + nt * 8 + tig * 2;
                const float b0 = fc1_b[col], b1 = fc1_b[col + 1];
                *(uint32_t*)&sAct[row * 264 + col] =
                    pack_h2(fmaxf(acc[mt][nt][0] + b0, 0.f),
                            fmaxf(acc[mt][nt][1] + b1, 0.f));
                *(uint32_t*)&sAct[(row + 8) * 264 + col] =
                    pack_h2(fmaxf(acc[mt][nt][2] + b0, 0.f),
                            fmaxf(acc[mt][nt][3] + b1, 0.f));
            }
        __syncthreads();
    }

    // ================= fc2 & fc3: K=256, 8 chunks =================
    for (int layer = 0; layer < 2; layer++) {
        const __half* wg = layer ? g_fc3h : g_fc2h;
        const float*  bg = layer ? fc3_b : fc2_b;
        #pragma unroll
        for (int mt = 0; mt < 2; mt++)
            #pragma unroll
            for (int nt = 0; nt < 8; nt++)
                #pragma unroll
                for (int q = 0; q < 4; q++) acc[mt][nt][q] = 0.f;

        auto issue2 = [&](int c) {
            const uint32_t bb = sBu + (uint32_t)(c % 3) * 20480;
            const __half* bsrc = wg + (size_t)rB * 256 + c * 32 + qB * 8;
            cp16(bb + (uint32_t)(rB * 40 + qB * 8) * 2, bsrc);
            cp16(bb + (uint32_t)((rB + 128) * 40 + qB * 8) * 2, bsrc + 128 * 256);
            CP_COMMIT();
        };
        issue2(0); issue2(1);

        for (int c = 0; c < 8; c++) {
            if (c + 2 < 8) { CP_WAIT1(); } else { CP_WAIT0(); }
            __syncthreads();
            if (c + 2 < 8) issue2(c + 2);
            const uint32_t bb = sBu + (uint32_t)(c % 3) * 20480;
            #pragma unroll
            for (int kk = 0; kk < 32; kk += 16) {
                const int kg = c * 32 + kk;
                uint32_t a0[4], a1[4];
                ldsm4(a0, cA0 + kg * 2);
                ldsm4(a1, cA1 + kg * 2);
                #pragma unroll
                for (int gn = 0; gn < 4; gn++) {
                    uint32_t bbv[4];
                    ldsm4(bbv, bb + relB[gn] + kk * 2);
                    mma_f16(acc[0][2 * gn],     a0, bbv[0], bbv[1]);
                    mma_f16(acc[0][2 * gn + 1], a0, bbv[2], bbv[3]);
                    mma_f16(acc[1][2 * gn],     a1, bbv[0], bbv[1]);
                    mma_f16(acc[1][2 * gn + 1], a1, bbv[2], bbv[3]);
                }
            }
        }
        __syncthreads();
        #pragma unroll
        for (int mt = 0; mt < 2; mt++)
            #pragma unroll
            for (int nt = 0; nt < 8; nt++) {
                const int row = wm * 32 + mt * 16 + g;
                const int col = wn * 64 + nt * 8 + tig * 2;
                const float b0 = bg[col], b1 = bg[col + 1];
                *(uint32_t*)&sAct[row * 264 + col] =
                    pack_h2(fmaxf(acc[mt][nt][0] + b0, 0.f),
                            fmaxf(acc[mt][nt][1] + b1, 0.f));
                *(uint32_t*)&sAct[(row + 8) * 264 + col] =
                    pack_h2(fmaxf(acc[mt][nt][2] + b0, 0.f),
                            fmaxf(acc[mt][nt][3] + b1, 0.f));
            }
        __syncthreads();
    }

    // ================= fcf: K=256, N=27 (pad 32) =================
    {
        __half* sB0 = (__half*)(smc + ML_B);
        for (int i = tid; i < 1056; i += 512)
            ((uint4*)sB0)[i] = ((const uint4*)g_fcfh)[i];
        __syncthreads();

        const int l2b = l & 15;
        const uint32_t bF = sBu +
            (uint32_t)((wn * 8 + (l2b & 7)) * 264 + ((l2b >> 3) & 1) * 8) * 2;

        float fa[2][4];
        #pragma unroll
        for (int mt = 0; mt < 2; mt++)
            #pragma unroll
            for (int q = 0; q < 4; q++) fa[mt][q] = 0.f;

        #pragma unroll 4
        for (int s = 0; s < 16; s++) {
            const int kg = s * 16;
            uint32_t a0[4], a1[4], bb[2];
            ldsm4(a0, cA0 + kg * 2);
            ldsm4(a1, cA1 + kg * 2);
            ldsm2(bb, bF + kg * 2);
            mma_f16(fa[0], a0, bb[0], bb[1]);
            mma_f16(fa[1], a1, bb[0], bb[1]);
        }

        #pragma unroll
        for (int mt = 0; mt < 2; mt++) {
            const int row = m0 + wm * 32 + mt * 16 + g;
            const int col = wn * 8 + tig * 2;
            #pragma unroll
            for (int h = 0; h < 2; h++) {
                const int rr = row + h * 8;
                if (rr < NP) {
                    if (col < 27)
                        out[(size_t)rr * 27 + col]     = fa[mt][h * 2 + 0] + fcf_b[col];
                    if (col + 1 < 27)
                        out[(size_t)rr * 27 + col + 1] = fa[mt][h * 2 + 1] + fcf_b[col + 1];
                }
            }
        }
    }
}

// ---------------------------------------------------------------------------
extern "C" void kernel_launch(void* const* d_in, const int* in_sizes, int n_in,
                              void* d_out, int out_size)
{
    const float* images  = (const float*)d_in[0];
    const float* conv1_w = (const float*)d_in[1];
    const float* conv1_b = (const float*)d_in[2];
    const float* conv2_w = (const float*)d_in[3];
    const float* conv2_b = (const float*)d_in[4];
    const float* fc1_w   = (const float*)d_in[5];
    const float* fc1_b   = (const float*)d_in[6];
    const float* fc2_w   = (const float*)d_in[7];
    const float* fc2_b   = (const float*)d_in[8];
    const float* fc3_w   = (const float*)d_in[9];
    const float* fc3_b   = (const float*)d_in[10];
    const float* fcf_w   = (const float*)d_in[11];
    const float* fcf_b   = (const float*)d_in[12];
    float* out = (float*)d_out;

    convert_kernel<<<1280, 256>>>(fc1_w, fc2_w, fc3_w, fcf_w, conv2_w);

    cudaFuncSetAttribute(conv_mma_kernel,
                         cudaFuncAttributeMaxDynamicSharedMemorySize, CV_SMEM);
    conv_mma_kernel<<<NP / 4, 256, CV_SMEM>>>(images, conv1_w, conv1_b, conv2_b);

    cudaFuncSetAttribute(mlp_mma_kernel,
                         cudaFuncAttributeMaxDynamicSharedMemorySize, ML_SMEM);
    mlp_mma_kernel<<<MROWS_PAD / 128, 512, ML_SMEM>>>(
        fc1_b, fc2_b, fc3_b, fcf_b, out);
}

// round 11
// speedup vs baseline: 6.9443x; 1.0470x over previous
#include <cuda_runtime.h>
#include <cuda_fp16.h>
#include <cstdint>

#define NP 76832          // 32 * 49 * 49 patches
#define HN 49
#define SLEN 104
#define MROWS_PAD 76928   // 601 * 128

// conv output scratch, fp16, layout [patch][pix*20 + oc] (zero-init; pad rows zero)
__device__ __half g_h2[(size_t)MROWS_PAD * 1280];
// pre-converted fp16 weights
__device__ __align__(16) __half g_fc1h[256 * 1280];   // K permuted to pix*20+oc
__device__ __align__(16) __half g_fc2h[256 * 256];
__device__ __align__(16) __half g_fc3h[256 * 256];
__device__ __align__(16) __half g_fcfh[32 * 264];     // zero-padded
__device__ __align__(16) __half g_w2h[3 * 24 * 80];   // [dy][oc][dx*24+ic], zero-pad
__device__ __align__(16) __half g_w1h[3 * 24 * 32];   // [dy][oc][dx*8+ic], zero-pad

// ---------------------------------------------------------------------------
__device__ __forceinline__ uint32_t s2u(const void* p) {
    return (uint32_t)__cvta_generic_to_shared(p);
}
__device__ __forceinline__ void ldsm4(uint32_t* r, uint32_t addr) {
    asm volatile("ldmatrix.sync.aligned.m8n8.x4.shared.b16 {%0,%1,%2,%3}, [%4];"
        : "=r"(r[0]), "=r"(r[1]), "=r"(r[2]), "=r"(r[3]) : "r"(addr));
}
__device__ __forceinline__ void ldsm2(uint32_t* r, uint32_t addr) {
    asm volatile("ldmatrix.sync.aligned.m8n8.x2.shared.b16 {%0,%1}, [%2];"
        : "=r"(r[0]), "=r"(r[1]) : "r"(addr));
}
__device__ __forceinline__ void mma_f16(float* c, const uint32_t* a,
                                        uint32_t b0, uint32_t b1) {
    asm volatile(
        "mma.sync.aligned.m16n8k16.row.col.f32.f16.f16.f32 "
        "{%0,%1,%2,%3}, {%4,%5,%6,%7}, {%8,%9}, {%0,%1,%2,%3};"
        : "+f"(c[0]), "+f"(c[1]), "+f"(c[2]), "+f"(c[3])
        : "r"(a[0]), "r"(a[1]), "r"(a[2]), "r"(a[3]), "r"(b0), "r"(b1));
}
__device__ __forceinline__ uint32_t pack_h2(float a, float b) {
    __half2 h = __floats2half2_rn(a, b);
    return *(uint32_t*)&h;
}
__device__ __forceinline__ void cp16(uint32_t dst, const void* src) {
    asm volatile("cp.async.ca.shared.global [%0], [%1], 16;"
        :: "r"(dst), "l"(src));
}
#define CP_COMMIT() asm volatile("cp.async.commit_group;" ::: "memory")
#define CP_WAIT0()  asm volatile("cp.async.wait_group 0;" ::: "memory")
#define CP_WAIT1()  asm volatile("cp.async.wait_group 1;" ::: "memory")

// ===========================================================================
// Kernel 0: one-shot fp16 weight conversion / re-layout
// ===========================================================================
__global__ __launch_bounds__(256) void convert_kernel(
    const float* __restrict__ fc1_w, const float* __restrict__ fc2_w,
    const float* __restrict__ fc3_w, const float* __restrict__ fcf_w,
    const float* __restrict__ w2, const float* __restrict__ w1)
{
    const int i = blockIdx.x * 256 + threadIdx.x;
    if (i < 256 * 1280) {
        int n = i / 1280, k = i % 1280;
        int oc = k / 64, pix = k % 64;
        g_fc1h[(size_t)n * 1280 + pix * 20 + oc] = __float2half(fc1_w[i]);
    }
    if (i < 256 * 256) {
        g_fc2h[i] = __float2half(fc2_w[i]);
        g_fc3h[i] = __float2half(fc3_w[i]);
    }
    if (i < 32 * 264) {
        int r = i / 264, k = i % 264;
        g_fcfh[i] = (r < 27 && k < 256) ? __float2half(fcf_w[r * 256 + k])
                                        : __half(0.f);
    }
    if (i < 3 * 24 * 80) {
        int dy = i / 1920, r = i % 1920, oc = r / 80, k = r % 80;
        int dx = k / 24, ic = k % 24;
        g_w2h[i] = (oc < 20 && k < 72 && ic < 20)
                 ? __float2half(w2[oc * 180 + ic * 9 + dy * 3 + dx]) : __half(0.f);
    }
    if (i < 3 * 24 * 32) {
        int dy = i / 768, r = i % 768, oc = r / 32, k = r % 32;
        int dx = k / 8, ic = k % 8;
        g_w1h[i] = (oc < 20 && dx < 3 && ic < 2)
                 ? __float2half(w1[oc * 18 + ic * 9 + dy * 3 + dx]) : __half(0.f);
    }
}

// ===========================================================================
// Kernel 1: conv1 + conv2, both fp16 mma with dx-packed K
// 4 patches / CTA, 256 threads = 8 warps (2 warps per patch). ~41KB smem.
// ===========================================================================
#define CV_H1   0          // 4*2400 + 16 pad = 9616 halves = 19232 B
#define CV_W2   19232      // 3*24*80 halves  = 11520 B  -> 30752
#define CV_INH  30752      // 4*100*8 halves  = 6400 B   -> 37152
#define CV_W1H  37152      // 3*24*32 halves  = 4608 B   -> 41760
#define CV_B1   41760      // 24 f32 = 96 B
#define CV_B2   41856      // 24 f32 = 96 B
#define CV_SMEM 41952

__global__ __launch_bounds__(256) void conv_mma_kernel(
    const float* __restrict__ images,
    const float* __restrict__ b1, const float* __restrict__ b2)
{
    extern __shared__ __align__(16) char smc[];
    __half* sH1  = (__half*)(smc + CV_H1);
    __half* sW2  = (__half*)(smc + CV_W2);
    __half* sInH = (__half*)(smc + CV_INH);
    __half* sW1h = (__half*)(smc + CV_W1H);
    float*  sB1  = (float*)(smc + CV_B1);
    float*  sB2  = (float*)(smc + CV_B2);

    const int tid = threadIdx.x;

    // zero-fill sH1 (pads must be finite/zero) and sInH (pad pixels + lanes)
    {
        uint32_t* z = (uint32_t*)smc;
        for (int i = tid; i < 19232 / 4; i += 256) z[i] = 0u;
        uint32_t* z2 = (uint32_t*)(smc + CV_INH);
        for (int i = tid; i < 6400 / 4; i += 256) z2[i] = 0u;
    }
    // copy pre-packed weights
    for (int i = tid; i < 720; i += 256)
        ((uint4*)sW2)[i] = ((const uint4*)g_w2h)[i];
    for (int i = tid; i < 288; i += 256)
        ((uint4*)sW1h)[i] = ((const uint4*)g_w1h)[i];
    if (tid < 24) {
        sB1[tid] = (tid < 20) ? b1[tid] : 0.f;
        sB2[tid] = (tid < 20) ? b2[tid] : 0.f;
    }

    const int lp  = tid >> 6;          // 0..3
    const int pix = tid & 63;
    const int y = pix >> 3, x = pix & 7;
    const int patch = blockIdx.x * 4 + lp;
    const int b  = patch / (HN * HN);
    const int t2 = patch % (HN * HN);
    const int i0 = (t2 / HN) * 2, j0 = (t2 % HN) * 2;
    __syncthreads();

    // ---- load input patch pixels as half2 (ch0, ch1), padded 10x10 ----
    {
        const float c0 = images[((size_t)(b * 2 + 0) * SLEN + (i0 + y)) * SLEN + (j0 + x)];
        const float c1 = images[((size_t)(b * 2 + 1) * SLEN + (i0 + y)) * SLEN + (j0 + x)];
        const int rr = (y + 1) * 10 + (x + 1);
        *(uint32_t*)&sInH[lp * 800 + rr * 8] = pack_h2(c0, c1);
    }
    __syncthreads();

    // ---- warp geometry (shared by both convs) ----
    const int l    = tid & 31;
    const int wid  = tid >> 5;
    const int lp_w = wid >> 1;
    const int hf   = wid & 1;
    const int g    = l >> 2;
    const int tig  = l & 3;
    const int l16  = l & 15, lg = l >> 4;

    const int pA0 = hf * 32 + l16;            // pixel for m16-tile row
    const int pA1 = pA0 + 16;
    const int rT0 = (pA0 >> 3) * 10 + (pA0 & 7);   // window top-left padded idx
    const int rT1 = (pA1 >> 3) * 10 + (pA1 & 7);

    // B-fragment lane addressing (rows = oc)
    const int bt   = l >> 3;
    const int bn01 = (bt >> 1) * 8 + (l & 7);
    const int bk01 = (bt & 1) * 8;
    const int l2   = l & 15;
    const int bn2  = 16 + (l2 & 7);
    const int bk2  = ((l2 >> 3) & 1) * 8;

    // ================= conv1 via fp16 mma (K = dx*8+ic per dy) =================
    {
        const uint32_t sInU = s2u(sInH + lp_w * 800);
        const uint32_t sW1u = s2u(sW1h);
        const uint32_t aI0 = sInU + (uint32_t)(rT0 * 8 + lg * 8) * 2;
        const uint32_t aI1 = sInU + (uint32_t)(rT1 * 8 + lg * 8) * 2;
        const uint32_t bW10 = sW1u + (uint32_t)(bn01 * 32 + bk01) * 2;
        const uint32_t bW12 = sW1u + (uint32_t)(bn2 * 32 + bk2) * 2;

        float acc1[2][3][4];
        #pragma unroll
        for (int mt = 0; mt < 2; mt++)
            #pragma unroll
            for (int nt = 0; nt < 3; nt++)
                #pragma unroll
                for (int q = 0; q < 4; q++) acc1[mt][nt][q] = 0.f;

        #pragma unroll
        for (int dy = 0; dy < 3; dy++) {
            const uint32_t ro = (uint32_t)dy * 160;    // +10 rows * 16 B
            const uint32_t wo = (uint32_t)dy * 1536;   // +768 halves * 2
            #pragma unroll
            for (int c = 0; c < 2; c++) {
                const uint32_t ko = (uint32_t)c * 32;
                uint32_t a0[4], a1[4], b01[4], bb2[2];
                ldsm4(a0, aI0 + ro + ko);
                ldsm4(a1, aI1 + ro + ko);
                ldsm4(b01, bW10 + wo + ko);
                ldsm2(bb2, bW12 + wo + ko);
                mma_f16(acc1[0][0], a0, b01[0], b01[1]);
                mma_f16(acc1[0][1], a0, b01[2], b01[3]);
                mma_f16(acc1[0][2], a0, bb2[0], bb2[1]);
                mma_f16(acc1[1][0], a1, b01[0], b01[1]);
                mma_f16(acc1[1][1], a1, b01[2], b01[3]);
                mma_f16(acc1[1][2], a1, bb2[0], bb2[1]);
            }
        }

        // epilogue: bias+relu -> sH1[lp][padded center pix][ic] stride 24
        __half* h1w = sH1 + lp_w * 2400;
        #pragma unroll
        for (int mt = 0; mt < 2; mt++) {
            const int row = hf * 32 + mt * 16 + g;          // pixel
            const int rc0 = ((row >> 3) + 1) * 10 + (row & 7) + 1;
            const int rc1 = (((row + 8) >> 3) + 1) * 10 + (row & 7) + 1;
            #pragma unroll
            for (int nt = 0; nt < 3; nt++) {
                const int col = nt * 8 + tig * 2;
                if (col < 20) {
                    const float v0 = sB1[col], v1 = sB1[col + 1];
                    *(uint32_t*)&h1w[rc0 * 24 + col] =
                        pack_h2(fmaxf(acc1[mt][nt][0] + v0, 0.f),
                                fmaxf(acc1[mt][nt][1] + v1, 0.f));
                    *(uint32_t*)&h1w[rc1 * 24 + col] =
                        pack_h2(fmaxf(acc1[mt][nt][2] + v0, 0.f),
                                fmaxf(acc1[mt][nt][3] + v1, 0.f));
                }
            }
        }
    }
    __syncthreads();

    // ================= conv2 via fp16 mma (K = dx*24+ic per dy) =================
    const uint32_t sH1u = s2u(sH1 + lp_w * 2400);
    const uint32_t sW2u = s2u(sW2);
    const uint32_t aB0 = sH1u + (uint32_t)(rT0 * 24 + lg * 8) * 2;
    const uint32_t aB1 = sH1u + (uint32_t)(rT1 * 24 + lg * 8) * 2;
    const uint32_t bB01 = sW2u + (uint32_t)(bn01 * 80 + bk01) * 2;
    const uint32_t bB2  = sW2u + (uint32_t)(bn2 * 80 + bk2) * 2;

    float acc[2][3][4];
    #pragma unroll
    for (int mt = 0; mt < 2; mt++)
        #pragma unroll
        for (int nt = 0; nt < 3; nt++)
            #pragma unroll
            for (int q = 0; q < 4; q++) acc[mt][nt][q] = 0.f;

    #pragma unroll
    for (int dy = 0; dy < 3; dy++) {
        const uint32_t ro = (uint32_t)dy * 480;    // +10 rows * 48 B
        const uint32_t wo = (uint32_t)dy * 3840;   // +24*80 halves * 2
        #pragma unroll
        for (int c = 0; c < 5; c++) {
            const uint32_t ko = (uint32_t)c * 32;
            uint32_t a0[4], a1[4], b01[4], bb2[2];
            ldsm4(a0, aB0 + ro + ko);
            ldsm4(a1, aB1 + ro + ko);
            ldsm4(b01, bB01 + wo + ko);
            ldsm2(bb2, bB2 + wo + ko);
            mma_f16(acc[0][0], a0, b01[0], b01[1]);
            mma_f16(acc[0][1], a0, b01[2], b01[3]);
            mma_f16(acc[0][2], a0, bb2[0], bb2[1]);
            mma_f16(acc[1][0], a1, b01[0], b01[1]);
            mma_f16(acc[1][1], a1, b01[2], b01[3]);
            mma_f16(acc[1][2], a1, bb2[0], bb2[1]);
        }
    }

    // ---- direct epilogue: bias+relu -> g_h2[patch][pix*20 + oc] ----
    {
        __half* dst = g_h2 + (size_t)(blockIdx.x * 4 + lp_w) * 1280;
        #pragma unroll
        for (int mt = 0; mt < 2; mt++) {
            const int row = hf * 32 + mt * 16 + g;
            #pragma unroll
            for (int nt = 0; nt < 3; nt++) {
                const int col = nt * 8 + tig * 2;
                if (col < 20) {
                    const float b0 = sB2[col], b1v = sB2[col + 1];
                    *(uint32_t*)&dst[row * 20 + col] =
                        pack_h2(fmaxf(acc[mt][nt][0] + b0, 0.f),
                                fmaxf(acc[mt][nt][1] + b1v, 0.f));
                    *(uint32_t*)&dst[(row + 8) * 20 + col] =
                        pack_h2(fmaxf(acc[mt][nt][2] + b0, 0.f),
                                fmaxf(acc[mt][nt][3] + b1v, 0.f));
                }
            }
        }
    }
}

// ===========================================================================
// Kernel 2: fused MLP, fp16 mma + ldmatrix + cp.async pipeline (3 bufs, depth 2)
// ===========================================================================
#define ML_ACT  0                       // 128 x 264 halves = 67584
#define ML_B    67584                   // 3 x (256 x 40 halves) = 3 x 20480
#define ML_A    (67584 + 61440)         // 3 x (128 x 40 halves) = 3 x 10240
#define ML_SMEM (67584 + 61440 + 30720) // 159744

__global__ __launch_bounds__(512, 1) void mlp_mma_kernel(
    const float* __restrict__ fc1_b, const float* __restrict__ fc2_b,
    const float* __restrict__ fc3_b, const float* __restrict__ fcf_b,
    float* __restrict__ out)
{
    extern __shared__ __align__(16) char smc[];
    __half* sAct = (__half*)(smc + ML_ACT);

    const int tid  = threadIdx.x;
    const int l    = tid & 31;
    const int wid  = tid >> 5;
    const int wm   = wid >> 2;
    const int wn   = wid & 3;
    const int g    = l >> 2;
    const int tig  = l & 3;
    const int m0   = blockIdx.x * 128;

    const uint32_t sActu = s2u(smc + ML_ACT);
    const uint32_t sBu   = s2u(smc + ML_B);
    const uint32_t sAu   = s2u(smc + ML_A);

    const int l16 = l & 15, lg = l >> 4;
    const uint32_t relA0 = (uint32_t)((wm * 32 + l16) * 40 + lg * 8) * 2;
    const uint32_t relA1 = relA0 + 16 * 40 * 2;
    const uint32_t cA0 = sActu + (uint32_t)((wm * 32 + l16) * 264 + lg * 8) * 2;
    const uint32_t cA1 = cA0 + 16 * 264 * 2;
    const int bt = l >> 3;
    const int bnl = (bt >> 1) * 8 + (l & 7);
    const int bkl = (bt & 1) * 8;
    uint32_t relB[4];
    #pragma unroll
    for (int gn = 0; gn < 4; gn++)
        relB[gn] = (uint32_t)((wn * 64 + gn * 16 + bnl) * 40 + bkl) * 2;

    const int rB = tid >> 2, qB = tid & 3;
    const int rA = tid >> 2, qA = tid & 3;

    float acc[2][8][4];

    // ================= fc1: K=1280, 40 chunks, A from g_h2 =================
    {
        #pragma unroll
        for (int mt = 0; mt < 2; mt++)
            #pragma unroll
            for (int nt = 0; nt < 8; nt++)
                #pragma unroll
                for (int q = 0; q < 4; q++) acc[mt][nt][q] = 0.f;

        auto issue1 = [&](int c) {
            const uint32_t bb = sBu + (uint32_t)(c % 3) * 20480;
            const uint32_t ab = sAu + (uint32_t)(c % 3) * 10240;
            const __half* bsrc = g_fc1h + (size_t)rB * 1280 + c * 32 + qB * 8;
            cp16(bb + (uint32_t)(rB * 40 + qB * 8) * 2, bsrc);
            cp16(bb + (uint32_t)((rB + 128) * 40 + qB * 8) * 2, bsrc + 128 * 1280);
            cp16(ab + (uint32_t)(rA * 40 + qA * 8) * 2,
                 g_h2 + (size_t)(m0 + rA) * 1280 + c * 32 + qA * 8);
            CP_COMMIT();
        };
        issue1(0); issue1(1);

        for (int c = 0; c < 40; c++) {
            if (c + 2 < 40) { CP_WAIT1(); } else { CP_WAIT0(); }
            __syncthreads();
            if (c + 2 < 40) issue1(c + 2);
            const uint32_t bb = sBu + (uint32_t)(c % 3) * 20480;
            const uint32_t ab = sAu + (uint32_t)(c % 3) * 10240;
            #pragma unroll
            for (int kk = 0; kk < 32; kk += 16) {
                uint32_t a0[4], a1[4];
                ldsm4(a0, ab + relA0 + kk * 2);
                ldsm4(a1, ab + relA1 + kk * 2);
                #pragma unroll
                for (int gn = 0; gn < 4; gn++) {
                    uint32_t bbv[4];
                    ldsm4(bbv, bb + relB[gn] + kk * 2);
                    mma_f16(acc[0][2 * gn],     a0, bbv[0], bbv[1]);
                    mma_f16(acc[0][2 * gn + 1], a0, bbv[2], bbv[3]);
                    mma_f16(acc[1][2 * gn],     a1, bbv[0], bbv[1]);
                    mma_f16(acc[1][2 * gn + 1], a1, bbv[2], bbv[3]);
                }
            }
        }
        __syncthreads();
        #pragma unroll
        for (int mt = 0; mt < 2; mt++)
            #pragma unroll
            for (int nt = 0; nt < 8; nt++) {
                const int row = wm * 32 + mt * 16 + g;
                const int col = wn * 64 + nt * 8 + tig * 2;
                const float b0 = fc1_b[col], b1 = fc1_b[col + 1];
                *(uint32_t*)&sAct[row * 264 + col] =
                    pack_h2(fmaxf(acc[mt][nt][0] + b0, 0.f),
                            fmaxf(acc[mt][nt][1] + b1, 0.f));
                *(uint32_t*)&sAct[(row + 8) * 264 + col] =
                    pack_h2(fmaxf(acc[mt][nt][2] + b0, 0.f),
                            fmaxf(acc[mt][nt][3] + b1, 0.f));
            }
        __syncthreads();
    }

    // ================= fc2 & fc3: K=256, 8 chunks =================
    for (int layer = 0; layer < 2; layer++) {
        const __half* wg = layer ? g_fc3h : g_fc2h;
        const float*  bg = layer ? fc3_b : fc2_b;
        #pragma unroll
        for (int mt = 0; mt < 2; mt++)
            #pragma unroll
            for (int nt = 0; nt < 8; nt++)
                #pragma unroll
                for (int q = 0; q < 4; q++) acc[mt][nt][q] = 0.f;

        auto issue2 = [&](int c) {
            const uint32_t bb = sBu + (uint32_t)(c % 3) * 20480;
            const __half* bsrc = wg + (size_t)rB * 256 + c * 32 + qB * 8;
            cp16(bb + (uint32_t)(rB * 40 + qB * 8) * 2, bsrc);
            cp16(bb + (uint32_t)((rB + 128) * 40 + qB * 8) * 2, bsrc + 128 * 256);
            CP_COMMIT();
        };
        issue2(0); issue2(1);

        for (int c = 0; c < 8; c++) {
            if (c + 2 < 8) { CP_WAIT1(); } else { CP_WAIT0(); }
            __syncthreads();
            if (c + 2 < 8) issue2(c + 2);
            const uint32_t bb = sBu + (uint32_t)(c % 3) * 20480;
            #pragma unroll
            for (int kk = 0; kk < 32; kk += 16) {
                const int kg = c * 32 + kk;
                uint32_t a0[4], a1[4];
                ldsm4(a0, cA0 + kg * 2);
                ldsm4(a1, cA1 + kg * 2);
                #pragma unroll
                for (int gn = 0; gn < 4; gn++) {
                    uint32_t bbv[4];
                    ldsm4(bbv, bb + relB[gn] + kk * 2);
                    mma_f16(acc[0][2 * gn],     a0, bbv[0], bbv[1]);
                    mma_f16(acc[0][2 * gn + 1], a0, bbv[2], bbv[3]);
                    mma_f16(acc[1][2 * gn],     a1, bbv[0], bbv[1]);
                    mma_f16(acc[1][2 * gn + 1], a1, bbv[2], bbv[3]);
                }
            }
        }
        __syncthreads();
        #pragma unroll
        for (int mt = 0; mt < 2; mt++)
            #pragma unroll
            for (int nt = 0; nt < 8; nt++) {
                const int row = wm * 32 + mt * 16 + g;
                const int col = wn * 64 + nt * 8 + tig * 2;
                const float b0 = bg[col], b1 = bg[col + 1];
                *(uint32_t*)&sAct[row * 264 + col] =
                    pack_h2(fmaxf(acc[mt][nt][0] + b0, 0.f),
                            fmaxf(acc[mt][nt][1] + b1, 0.f));
                *(uint32_t*)&sAct[(row + 8) * 264 + col] =
                    pack_h2(fmaxf(acc[mt][nt][2] + b0, 0.f),
                            fmaxf(acc[mt][nt][3] + b1, 0.f));
            }
        __syncthreads();
    }

    // ================= fcf: K=256, N=27 (pad 32) =================
    {
        __half* sB0 = (__half*)(smc + ML_B);
        for (int i = tid; i < 1056; i += 512)
            ((uint4*)sB0)[i] = ((const uint4*)g_fcfh)[i];
        __syncthreads();

        const int l2b = l & 15;
        const uint32_t bF = sBu +
            (uint32_t)((wn * 8 + (l2b & 7)) * 264 + ((l2b >> 3) & 1) * 8) * 2;

        float fa[2][4];
        #pragma unroll
        for (int mt = 0; mt < 2; mt++)
            #pragma unroll
            for (int q = 0; q < 4; q++) fa[mt][q] = 0.f;

        #pragma unroll 4
        for (int s = 0; s < 16; s++) {
            const int kg = s * 16;
            uint32_t a0[4], a1[4], bb[2];
            ldsm4(a0, cA0 + kg * 2);
            ldsm4(a1, cA1 + kg * 2);
            ldsm2(bb, bF + kg * 2);
            mma_f16(fa[0], a0, bb[0], bb[1]);
            mma_f16(fa[1], a1, bb[0], bb[1]);
        }

        #pragma unroll
        for (int mt = 0; mt < 2; mt++) {
            const int row = m0 + wm * 32 + mt * 16 + g;
            const int col = wn * 8 + tig * 2;
            #pragma unroll
            for (int h = 0; h < 2; h++) {
                const int rr = row + h * 8;
                if (rr < NP) {
                    if (col < 27)
                        out[(size_t)rr * 27 + col]     = fa[mt][h * 2 + 0] + fcf_b[col];
                    if (col + 1 < 27)
                        out[(size_t)rr * 27 + col + 1] = fa[mt][h * 2 + 1] + fcf_b[col + 1];
                }
            }
        }
    }
}

// ---------------------------------------------------------------------------
extern "C" void kernel_launch(void* const* d_in, const int* in_sizes, int n_in,
                              void* d_out, int out_size)
{
    const float* images  = (const float*)d_in[0];
    const float* conv1_w = (const float*)d_in[1];
    const float* conv1_b = (const float*)d_in[2];
    const float* conv2_w = (const float*)d_in[3];
    const float* conv2_b = (const float*)d_in[4];
    const float* fc1_w   = (const float*)d_in[5];
    const float* fc1_b   = (const float*)d_in[6];
    const float* fc2_w   = (const float*)d_in[7];
    const float* fc2_b   = (const float*)d_in[8];
    const float* fc3_w   = (const float*)d_in[9];
    const float* fc3_b   = (const float*)d_in[10];
    const float* fcf_w   = (const float*)d_in[11];
    const float* fcf_b   = (const float*)d_in[12];
    float* out = (float*)d_out;

    convert_kernel<<<1280, 256>>>(fc1_w, fc2_w, fc3_w, fcf_w, conv2_w, conv1_w);

    cudaFuncSetAttribute(conv_mma_kernel,
                         cudaFuncAttributeMaxDynamicSharedMemorySize, CV_SMEM);
    conv_mma_kernel<<<NP / 4, 256, CV_SMEM>>>(images, conv1_b, conv2_b);

    cudaFuncSetAttribute(mlp_mma_kernel,
                         cudaFuncAttributeMaxDynamicSharedMemorySize, ML_SMEM);
    mlp_mma_kernel<<<MROWS_PAD / 128, 512, ML_SMEM>>>(
        fc1_b, fc2_b, fc3_b, fcf_b, out);
}